// round 6
// baseline (speedup 1.0000x reference)
#include <cuda_runtime.h>
#include <math.h>
#include <stdint.h>
#include <stddef.h>

#define NB 64
#define NT 80
#define NF 4096
#define NH 512
#define NG 1536
#define NWD 6000
#define NL 32
#define BHSZ (NB*NH)
#define OUTROW ((size_t)NL*NWD)

#define HP 516
#define WP 66
#define PBS (12*64)
#define SMEM_FLOATS (64*HP + 8*12*WP + 8*PBS)
#define SMEM_BYTES (SMEM_FLOATS*4)

__device__ float g_gi [NT*NB*NG];     // gi_v -> enc-c chain -> dec gh (needs >= 3.15M; has 7.86M)
__device__ float g_gic[NT*NB*NG];     // gi_c -> dec gi (3.15M <= 7.86M ok)
__device__ float g_enc[NT*NB*NH];     // enc-v chain (= enc_out) ONLY — never the 2048x1536 gemm!
__device__ float g_h0 [BHSZ];         // zeros (never written)
__device__ float g_hvall[32*BHSZ];
__device__ float g_hcall[32*BHSZ];
__device__ float g_lpart[NB];
__device__ unsigned g_barrier;

#define FMA2(d,a,b) asm("fma.rn.f32x2 %0, %1, %2, %0;" : "+l"(d) : "l"(a), "l"(b))
#define DUP(d,v)    asm("mov.b64 %0,{%1,%1};" : "=l"(d) : "f"(v))
#define UNPK(lo,hi,d) asm("mov.b64 {%0,%1}, %2;" : "=f"(lo), "=f"(hi) : "l"(d))
__device__ __forceinline__ float sigm(float x){ return 1.f/(1.f+expf(-x)); }

__device__ __forceinline__ void gridbar(unsigned& gen){
    __syncthreads();
    if (threadIdx.x == 0){
        gen += gridDim.x;
        asm volatile("red.release.gpu.global.add.u32 [%0], %1;" :: "l"(&g_barrier), "r"(1u) : "memory");
        unsigned v;
        do {
            __nanosleep(20);
            asm volatile("ld.acquire.gpu.global.u32 %0, [%1];" : "=r"(v) : "l"(&g_barrier) : "memory");
        } while (v < gen);
    }
    __syncthreads();
}

// ================= big GEMM: C[m,n] = sum_k A[m,k]*B[n,k] + bias[n] =================
// tile 128x128, BK=16, 256 threads, 8x8 microtile, f32x2 accum along n.
// amode=1: A row m -> x[(m&63)*NT + (m>>6)].  cmode=1: C row m -> out[(m&63)*OUTROW + ((m>>6)+1)*NWD]
__global__ __launch_bounds__(256) void gemm2_k(
    const float* __restrict__ A, const float* __restrict__ B,
    const float* __restrict__ bias, float* __restrict__ C,
    int Mreal, int N, int K, int lda, int ldb, int ldc, int amode, int cmode)
{
    __shared__ __align__(16) float Asd[16*128*2];
    __shared__ __align__(16) float Bsf[16*64*2];
    const int tid = threadIdx.x;
    const int bn0 = blockIdx.x * 128;
    const int bm0 = blockIdx.y * 128;

    const int sm_ = tid & 127;
    const int sh  = tid >> 7;
    const int gm  = bm0 + sm_;
    const float* arow;
    if (amode == 1){ int b_ = gm & 63, t_ = gm >> 6; arow = A + ((size_t)b_*NT + t_)*(size_t)lda; }
    else arow = A + (size_t)gm*(size_t)lda;
    const int gn = bn0 + sm_;
    const float* brow = B + (size_t)gn*(size_t)ldb;
    const bool bok = gn < N;

    const int ty = tid >> 4, tx = tid & 15;

    unsigned long long acc[8][4];
    #pragma unroll
    for (int i = 0; i < 8; i++){ acc[i][0]=0ull; acc[i][1]=0ull; acc[i][2]=0ull; acc[i][3]=0ull; }

    float4 ra0, ra1, rb0, rb1;
    ra0 = *(const float4*)(arow + (sh*2+0)*4);
    ra1 = *(const float4*)(arow + (sh*2+1)*4);
    rb0 = bok ? *(const float4*)(brow + (sh*2+0)*4) : make_float4(0,0,0,0);
    rb1 = bok ? *(const float4*)(brow + (sh*2+1)*4) : make_float4(0,0,0,0);

    const int nslices = K / 16;
    for (int s = 0; s < nslices; s++){
        {
            float av[8] = {ra0.x,ra0.y,ra0.z,ra0.w,ra1.x,ra1.y,ra1.z,ra1.w};
            #pragma unroll
            for (int e = 0; e < 8; e++){
                int k = sh*8 + e;
                unsigned long long d; DUP(d, av[e]);
                *(unsigned long long*)&Asd[(k*128 + sm_)*2] = d;
            }
            float bv[8] = {rb0.x,rb0.y,rb0.z,rb0.w,rb1.x,rb1.y,rb1.z,rb1.w};
            int p = sm_ >> 1, h = sm_ & 1;
            int swz = ((p & 3) << 4) | (p >> 2);
            #pragma unroll
            for (int e = 0; e < 8; e++){
                int k = sh*8 + e;
                Bsf[(k*64 + swz)*2 + h] = bv[e];
            }
        }
        __syncthreads();
        if (s + 1 < nslices){
            int kk = (s+1)*16;
            ra0 = *(const float4*)(arow + kk + (sh*2+0)*4);
            ra1 = *(const float4*)(arow + kk + (sh*2+1)*4);
            rb0 = bok ? *(const float4*)(brow + kk + (sh*2+0)*4) : make_float4(0,0,0,0);
            rb1 = bok ? *(const float4*)(brow + kk + (sh*2+1)*4) : make_float4(0,0,0,0);
        }
        #pragma unroll
        for (int k = 0; k < 16; k++){
            ulonglong2 a01 = *(const ulonglong2*)&Asd[(k*128 + ty*8 + 0)*2];
            ulonglong2 a23 = *(const ulonglong2*)&Asd[(k*128 + ty*8 + 2)*2];
            ulonglong2 a45 = *(const ulonglong2*)&Asd[(k*128 + ty*8 + 4)*2];
            ulonglong2 a67 = *(const ulonglong2*)&Asd[(k*128 + ty*8 + 6)*2];
            unsigned long long av[8] = {a01.x,a01.y,a23.x,a23.y,a45.x,a45.y,a67.x,a67.y};
            unsigned long long bv[4];
            #pragma unroll
            for (int j = 0; j < 4; j++)
                bv[j] = *(const unsigned long long*)&Bsf[(k*64 + (j<<4) + tx)*2];
            #pragma unroll
            for (int i = 0; i < 8; i++){
                FMA2(acc[i][0], av[i], bv[0]);
                FMA2(acc[i][1], av[i], bv[1]);
                FMA2(acc[i][2], av[i], bv[2]);
                FMA2(acc[i][3], av[i], bv[3]);
            }
        }
        __syncthreads();
    }

    #pragma unroll
    for (int i = 0; i < 8; i++){
        int m = bm0 + ty*8 + i;
        if (m >= Mreal) break;
        float* crow;
        if (cmode == 1) crow = C + (size_t)(m & 63)*OUTROW + (size_t)((m >> 6) + 1)*NWD;
        else            crow = C + (size_t)m*ldc;
        #pragma unroll
        for (int j = 0; j < 4; j++){
            int n = bn0 + tx*8 + 2*j;
            if (n + 1 < N){
                float lo, hi; UNPK(lo, hi, acc[i][j]);
                float2 v = make_float2(lo + bias[n], hi + bias[n+1]);
                *(float2*)(crow + n) = v;
            } else if (n < N){
                float lo, hi; UNPK(lo, hi, acc[i][j]);
                crow[n] = lo + bias[n];
            }
        }
    }
}

// ================= persistent scan =================
__device__ __forceinline__ void stage_h(const float* __restrict__ src, float* __restrict__ hs){
    int t = threadIdx.x;
    #pragma unroll
    for (int i = 0; i < 32; i++){
        int lin = (i*256 + t)*4;
        int b = lin >> 9, k = lin & 511;
        *(float4*)(hs + b*HP + k) = *(const float4*)(src + lin);
    }
}
__device__ __forceinline__ void stage_w(const float* __restrict__ W, int ld, int base,
                                        int kbase, float* __restrict__ dst){
    int lane = threadIdx.x & 31;
    #pragma unroll
    for (int r = 0; r < 12; r++){
        int row = (r>>2)*NH + base + (r&3);
        float2 v = *(const float2*)(W + (size_t)row*ld + kbase + 2*lane);
        *(float2*)(dst + r*WP + 2*lane) = v;
    }
    __syncwarp();
}
__device__ __forceinline__ void micro_mm(const float* __restrict__ hs,
                                         const float* __restrict__ wr,
                                         float* __restrict__ pb, int kbase){
    int lane = threadIdx.x & 31;
    int cjp = lane & 3, mg = lane >> 2;
    unsigned long long acc[8][3];
    #pragma unroll
    for (int i = 0; i < 8; i++){ acc[i][0]=0ull; acc[i][1]=0ull; acc[i][2]=0ull; }
    const float* hp = hs + mg*HP + kbase;
    const float* w0 = wr + cjp*WP;
    #pragma unroll 4
    for (int k = 0; k < 64; k += 2){
        unsigned long long wv0 = *(const unsigned long long*)(w0 + k);
        unsigned long long wv1 = *(const unsigned long long*)(w0 + 4*WP + k);
        unsigned long long wv2 = *(const unsigned long long*)(w0 + 8*WP + k);
        #pragma unroll
        for (int i = 0; i < 8; i++){
            unsigned long long a = *(const unsigned long long*)(hp + i*8*HP + k);
            FMA2(acc[i][0], a, wv0);
            FMA2(acc[i][1], a, wv1);
            FMA2(acc[i][2], a, wv2);
        }
    }
    #pragma unroll
    for (int i = 0; i < 8; i++){
        int m = mg + 8*i;
        #pragma unroll
        for (int g = 0; g < 3; g++){
            float lo, hi; UNPK(lo, hi, acc[i][g]);
            pb[(g*4 + cjp)*64 + m] = lo + hi;
        }
    }
}
__device__ __forceinline__ float psum(const float* __restrict__ pbuf, int r, int b){
    float s = 0.f;
    #pragma unroll
    for (int w = 0; w < 8; w++) s += pbuf[(w*12 + r)*64 + b];
    return s;
}

__global__ __launch_bounds__(256,1) void scan_k(
    const float* __restrict__ Whh, const float* __restrict__ bhh,
    const float* __restrict__ bih, const float* __restrict__ gi_all,
    const float* __restrict__ h0, float* __restrict__ chain, int steps)
{
    extern __shared__ float sm[];
    float* hs = sm;
    float* wst = sm + 64*HP;
    float* pbuf = wst + 8*12*WP;
    const int tid = threadIdx.x, w = tid >> 5;
    const int c0 = blockIdx.x*4, kbase = w*64;
    float* wstw = wst + w*12*WP;
    float* pbw = pbuf + w*PBS;
    const int b = tid & 63, cj = tid >> 6;
    const int c = c0 + cj;
    unsigned gen = 0;

    stage_w(Whh, NH, c0, kbase, wstw);
    const float bhr = bhh[c], bhz = bhh[NH+c], bhn = bhh[2*NH+c];

    for (int step = 0; step < steps; step++){
        const float* hin = step ? (chain + (size_t)(step-1)*BHSZ) : h0;
        float* hout = chain + (size_t)step*BHSZ;
        const float* gp = gi_all ? (gi_all + ((size_t)step*NB + b)*NG) : bih;
        float gir = gp[c], giz = gp[NH+c], gin = gp[2*NH+c];
        stage_h(hin, hs);
        __syncthreads();
        micro_mm(hs, wstw, pbw, kbase);
        __syncthreads();
        {
            float ghr = bhr + psum(pbuf, cj, b);
            float ghz = bhz + psum(pbuf, 4+cj, b);
            float ghn = bhn + psum(pbuf, 8+cj, b);
            float r  = sigm(gir + ghr);
            float z  = sigm(giz + ghz);
            float nn = tanhf(gin + r*ghn);
            hout[b*NH + c] = (1.f - z)*nn + z*hs[b*HP + c];
        }
        gridbar(gen);
    }
}

// ================= batched decoder gates =================
__global__ void dec_gates_k(const float* __restrict__ gi_all, const float* __restrict__ gh_all,
                            const float* __restrict__ hv_all, const float* __restrict__ Wc,
                            const int* __restrict__ y, float* __restrict__ hc_all)
{
    int idx = blockIdx.x*blockDim.x + threadIdx.x;
    if (idx >= (NL-1)*BHSZ) return;
    int s = idx / BHSZ, r = idx % BHSZ;
    int b = r >> 9, c = r & 511;
    size_t m = (size_t)s*NB + b;
    const float* gi = gi_all + m*NG;
    const float* gh = gh_all + m*NG;
    int yb = y[s*NB + b];
    float gir = gi[c]      + Wc[(size_t)c*(NH+NWD)        + NH + yb];
    float giz = gi[NH+c]   + Wc[(size_t)(NH+c)*(NH+NWD)   + NH + yb];
    float gin = gi[2*NH+c] + Wc[(size_t)(2*NH+c)*(NH+NWD) + NH + yb];
    float rr = sigm(gir + gh[c]);
    float zz = sigm(giz + gh[NH+c]);
    float nn = tanhf(gin + rr*gh[2*NH+c]);
    hc_all[(size_t)s*BHSZ + r] = (1.f - zz)*nn + zz*hv_all[(size_t)s*BHSZ + r];
}

// ================= misc =================
__global__ void init_k(float* __restrict__ out){
    int idx = blockIdx.x*blockDim.x + threadIdx.x;
    if (idx < NB*NWD){
        int b = idx / NWD, n = idx % NWD;
        out[(size_t)b*OUTROW + n] = (b == 0 && n == 1) ? 1.f : 0.f;
    }
    if (idx < BHSZ) g_h0[idx] = 0.f;   // belt & braces
    if (idx == 0) g_barrier = 0u;
}
__global__ void bar0_k(){ if (threadIdx.x == 0) g_barrier = 0u; }
__global__ void loss1_k(const float* __restrict__ out, const int* __restrict__ y,
                        float* __restrict__ part){
    int b = blockIdx.x;
    const float* row = out + (size_t)b*OUTROW + (size_t)(NL-1)*NWD;
    __shared__ float red[256];
    float m = -1e30f;
    for (int i = threadIdx.x; i < NWD; i += 256) m = fmaxf(m, row[i]);
    red[threadIdx.x] = m; __syncthreads();
    for (int s = 128; s > 0; s >>= 1){ if (threadIdx.x < s) red[threadIdx.x] = fmaxf(red[threadIdx.x], red[threadIdx.x+s]); __syncthreads(); }
    m = red[0]; __syncthreads();
    float sum = 0.f;
    for (int i = threadIdx.x; i < NWD; i += 256) sum += expf(row[i] - m);
    red[threadIdx.x] = sum; __syncthreads();
    for (int s = 128; s > 0; s >>= 1){ if (threadIdx.x < s) red[threadIdx.x] += red[threadIdx.x+s]; __syncthreads(); }
    if (threadIdx.x == 0){
        int t = y[(NL-1)*NB + b];
        part[b] = -(row[t] - m - logf(red[0]));
    }
}
__global__ void loss2_k(const float* __restrict__ part, float* __restrict__ out){
    if (threadIdx.x == 0){
        float s = 0.f;
        for (int b = 0; b < NB; b++) s += part[b];
        out[(size_t)NB*NL*NWD] = s/(float)NB;
    }
}

extern "C" void kernel_launch(void* const* d_in, const int* in_sizes, int n_in,
                              void* d_out, int out_size){
    const float* x     = (const float*)d_in[0];
    const int*   y     = (const int*)  d_in[1];
    const float* Wih_v = (const float*)d_in[2];
    const float* Whh_v = (const float*)d_in[3];
    const float* bih_v = (const float*)d_in[4];
    const float* bhh_v = (const float*)d_in[5];
    const float* Wih_c = (const float*)d_in[6];
    const float* Whh_c = (const float*)d_in[7];
    const float* bih_c = (const float*)d_in[8];
    const float* bhh_c = (const float*)d_in[9];
    const float* Wout  = (const float*)d_in[10];
    const float* bout  = (const float*)d_in[11];
    float* out = (float*)d_out;

    float *gi, *gic, *enc, *h0, *hvall, *hcall, *lp;
    cudaGetSymbolAddress((void**)&gi,    g_gi);
    cudaGetSymbolAddress((void**)&gic,   g_gic);
    cudaGetSymbolAddress((void**)&enc,   g_enc);
    cudaGetSymbolAddress((void**)&h0,    g_h0);
    cudaGetSymbolAddress((void**)&hvall, g_hvall);
    cudaGetSymbolAddress((void**)&hcall, g_hcall);
    cudaGetSymbolAddress((void**)&lp,    g_lpart);

    cudaFuncSetAttribute(scan_k, cudaFuncAttributeMaxDynamicSharedMemorySize, SMEM_BYTES);

    init_k<<<(NB*NWD + 255)/256, 256>>>(out);

    // gi_v = x @ Wih_v^T + bih_v   (5120 x 1536 x 4096) -> g_gi
    gemm2_k<<<dim3(NG/128, NT*NB/128), 256>>>(x, Wih_v, bih_v, gi,
        NT*NB, NG, NF, NF, NF, NG, 1, 0);

    // encoder-v: chain = g_enc (== enc_out)
    scan_k<<<128, 256, SMEM_BYTES>>>(Whh_v, bhh_v, nullptr, gi, h0, enc, NT);

    // gi_c = enc_out @ Wih_c[:, :H]^T + bih_c -> g_gic
    gemm2_k<<<dim3(NG/128, NT*NB/128), 256>>>(enc, Wih_c, bih_c, gic,
        NT*NB, NG, NH, NH, NH+NWD, NG, 0, 0);

    bar0_k<<<1, 32>>>();
    // encoder-c: chain = g_gi (gi_v dead)
    scan_k<<<128, 256, SMEM_BYTES>>>(Whh_c, bhh_c, nullptr, gic, h0, gi, NT);

    bar0_k<<<1, 32>>>();
    // decoder h_v chain: h0 = chain_c[79], 31 steps, gi = bih_v
    scan_k<<<128, 256, SMEM_BYTES>>>(Whh_v, bhh_v, bih_v, nullptr,
        gi + (size_t)(NT-1)*BHSZ, hvall, NL-1);

    // batched decoder (note buffer fix: gh -> g_gi which holds 7.86M floats;
    // g_enc is only 2.62M and CANNOT hold a 2048x1536 result)
    gemm2_k<<<dim3(NG/128, 16), 256>>>(hvall, Wih_c, bih_c, gic,
        2048, NG, NH, NH, NH+NWD, NG, 0, 0);
    gemm2_k<<<dim3(NG/128, 16), 256>>>(hvall, Whh_c, bhh_c, gi,
        2048, NG, NH, NH, NH, NG, 0, 0);
    dec_gates_k<<<((NL-1)*BHSZ + 255)/256, 256>>>(gic, gi, hvall, Wih_c, y, hcall);
    // logits = hc_all @ Wout^T + bout -> probs[:, s+1, :]
    gemm2_k<<<dim3((NWD + 127)/128, 16), 256>>>(hcall, Wout, bout, out,
        (NL-1)*NB, NWD, NH, NH, NH, 0, 0, 1);

    loss1_k<<<NB, 256>>>(out, y, lp);
    loss2_k<<<1, 32>>>(lp, out);
}

// round 7
// speedup vs baseline: 1.0963x; 1.0963x over previous
#include <cuda_runtime.h>
#include <math.h>
#include <stdint.h>
#include <stddef.h>

#define NB 64
#define NT 80
#define NF 4096
#define NH 512
#define NG 1536
#define NWD 6000
#define NL 32
#define BHSZ (NB*NH)
#define OUTROW ((size_t)NL*NWD)

#define HP 516
#define WP 66
#define PBS (12*64)
#define SMEM_FLOATS (64*HP + 8*12*WP + 8*PBS)
#define SMEM_BYTES (SMEM_FLOATS*4)

__device__ float g_gi [NT*NB*NG];     // gi_v -> enc-c chain -> dec gh
__device__ float g_gic[NT*NB*NG];     // gi_c -> dec gi
__device__ float g_enc[NT*NB*NH];     // enc-v chain (= enc_out) ONLY
__device__ float g_h0 [BHSZ];         // zeros
__device__ float g_hvall[32*BHSZ];
__device__ float g_hcall[32*BHSZ];
__device__ float g_lpart[NB];
__device__ unsigned g_barrier;

#define FMA2(d,a,b) asm("fma.rn.f32x2 %0, %1, %2, %0;" : "+l"(d) : "l"(a), "l"(b))
#define DUP(d,v)    asm("mov.b64 %0,{%1,%1};" : "=l"(d) : "f"(v))
#define UNPK(lo,hi,d) asm("mov.b64 {%0,%1}, %2;" : "=f"(lo), "=f"(hi) : "l"(d))
__device__ __forceinline__ float sigm(float x){ return 1.f/(1.f+expf(-x)); }

__device__ __forceinline__ void gridbar(unsigned& gen){
    __syncthreads();
    if (threadIdx.x == 0){
        gen += gridDim.x;
        asm volatile("red.release.gpu.global.add.u32 [%0], %1;" :: "l"(&g_barrier), "r"(1u) : "memory");
        unsigned v;
        do {
            __nanosleep(20);
            asm volatile("ld.acquire.gpu.global.u32 %0, [%1];" : "=r"(v) : "l"(&g_barrier) : "memory");
        } while (v < gen);
    }
    __syncthreads();
}

// ================= big GEMM: C[m,n] = sum_k A[m,k]*B[n,k] + bias[n] =================
// tile 128x128, BK=16, 256 threads, 8x8 microtile, f32x2 accum along n.
// __launch_bounds__(256,2): cap 128 regs -> 2 blocks/SM (was 144 regs, 1 block/SM, occ 12.5%)
__global__ __launch_bounds__(256, 2) void gemm2_k(
    const float* __restrict__ A, const float* __restrict__ B,
    const float* __restrict__ bias, float* __restrict__ C,
    int Mreal, int N, int K, int lda, int ldb, int ldc, int amode, int cmode)
{
    __shared__ __align__(16) float Asd[16*128*2];
    __shared__ __align__(16) float Bsf[16*64*2];
    const int tid = threadIdx.x;
    const int bn0 = blockIdx.x * 128;
    const int bm0 = blockIdx.y * 128;

    const int sm_ = tid & 127;
    const int sh  = tid >> 7;
    const int gm  = bm0 + sm_;
    const float* arow;
    if (amode == 1){ int b_ = gm & 63, t_ = gm >> 6; arow = A + ((size_t)b_*NT + t_)*(size_t)lda; }
    else arow = A + (size_t)gm*(size_t)lda;
    const int gn = bn0 + sm_;
    const float* brow = B + (size_t)gn*(size_t)ldb;
    const bool bok = gn < N;

    const int ty = tid >> 4, tx = tid & 15;

    unsigned long long acc[8][4];
    #pragma unroll
    for (int i = 0; i < 8; i++){ acc[i][0]=0ull; acc[i][1]=0ull; acc[i][2]=0ull; acc[i][3]=0ull; }

    float4 ra0, ra1, rb0, rb1;
    ra0 = *(const float4*)(arow + (sh*2+0)*4);
    ra1 = *(const float4*)(arow + (sh*2+1)*4);
    rb0 = bok ? *(const float4*)(brow + (sh*2+0)*4) : make_float4(0,0,0,0);
    rb1 = bok ? *(const float4*)(brow + (sh*2+1)*4) : make_float4(0,0,0,0);

    const int nslices = K / 16;
    for (int s = 0; s < nslices; s++){
        {
            float av[8] = {ra0.x,ra0.y,ra0.z,ra0.w,ra1.x,ra1.y,ra1.z,ra1.w};
            #pragma unroll
            for (int e = 0; e < 8; e++){
                int k = sh*8 + e;
                unsigned long long d; DUP(d, av[e]);
                *(unsigned long long*)&Asd[(k*128 + sm_)*2] = d;
            }
            float bv[8] = {rb0.x,rb0.y,rb0.z,rb0.w,rb1.x,rb1.y,rb1.z,rb1.w};
            int p = sm_ >> 1, h = sm_ & 1;
            int swz = ((p & 3) << 4) | (p >> 2);
            #pragma unroll
            for (int e = 0; e < 8; e++){
                int k = sh*8 + e;
                Bsf[(k*64 + swz)*2 + h] = bv[e];
            }
        }
        __syncthreads();
        if (s + 1 < nslices){
            int kk = (s+1)*16;
            ra0 = *(const float4*)(arow + kk + (sh*2+0)*4);
            ra1 = *(const float4*)(arow + kk + (sh*2+1)*4);
            rb0 = bok ? *(const float4*)(brow + kk + (sh*2+0)*4) : make_float4(0,0,0,0);
            rb1 = bok ? *(const float4*)(brow + kk + (sh*2+1)*4) : make_float4(0,0,0,0);
        }
        #pragma unroll
        for (int k = 0; k < 16; k++){
            ulonglong2 a01 = *(const ulonglong2*)&Asd[(k*128 + ty*8 + 0)*2];
            ulonglong2 a23 = *(const ulonglong2*)&Asd[(k*128 + ty*8 + 2)*2];
            ulonglong2 a45 = *(const ulonglong2*)&Asd[(k*128 + ty*8 + 4)*2];
            ulonglong2 a67 = *(const ulonglong2*)&Asd[(k*128 + ty*8 + 6)*2];
            unsigned long long av[8] = {a01.x,a01.y,a23.x,a23.y,a45.x,a45.y,a67.x,a67.y};
            unsigned long long bv[4];
            #pragma unroll
            for (int j = 0; j < 4; j++)
                bv[j] = *(const unsigned long long*)&Bsf[(k*64 + (j<<4) + tx)*2];
            #pragma unroll
            for (int i = 0; i < 8; i++){
                FMA2(acc[i][0], av[i], bv[0]);
                FMA2(acc[i][1], av[i], bv[1]);
                FMA2(acc[i][2], av[i], bv[2]);
                FMA2(acc[i][3], av[i], bv[3]);
            }
        }
        __syncthreads();
    }

    #pragma unroll
    for (int i = 0; i < 8; i++){
        int m = bm0 + ty*8 + i;
        if (m >= Mreal) break;
        float* crow;
        if (cmode == 1) crow = C + (size_t)(m & 63)*OUTROW + (size_t)((m >> 6) + 1)*NWD;
        else            crow = C + (size_t)m*ldc;
        #pragma unroll
        for (int j = 0; j < 4; j++){
            int n = bn0 + tx*8 + 2*j;
            if (n + 1 < N){
                float lo, hi; UNPK(lo, hi, acc[i][j]);
                float2 v = make_float2(lo + bias[n], hi + bias[n+1]);
                *(float2*)(crow + n) = v;
            } else if (n < N){
                float lo, hi; UNPK(lo, hi, acc[i][j]);
                crow[n] = lo + bias[n];
            }
        }
    }
}

// ================= persistent scan =================
__device__ __forceinline__ void stage_h(const float* __restrict__ src, float* __restrict__ hs){
    int t = threadIdx.x;
    #pragma unroll
    for (int i = 0; i < 32; i++){
        int lin = (i*256 + t)*4;
        int b = lin >> 9, k = lin & 511;
        *(float4*)(hs + b*HP + k) = *(const float4*)(src + lin);
    }
}
__device__ __forceinline__ void stage_w(const float* __restrict__ W, int ld, int base,
                                        int kbase, float* __restrict__ dst){
    int lane = threadIdx.x & 31;
    #pragma unroll
    for (int r = 0; r < 12; r++){
        int row = (r>>2)*NH + base + (r&3);
        float2 v = *(const float2*)(W + (size_t)row*ld + kbase + 2*lane);
        *(float2*)(dst + r*WP + 2*lane) = v;
    }
    __syncwarp();
}
__device__ __forceinline__ void micro_mm(const float* __restrict__ hs,
                                         const float* __restrict__ wr,
                                         float* __restrict__ pb, int kbase){
    int lane = threadIdx.x & 31;
    int cjp = lane & 3, mg = lane >> 2;
    unsigned long long acc[8][3];
    #pragma unroll
    for (int i = 0; i < 8; i++){ acc[i][0]=0ull; acc[i][1]=0ull; acc[i][2]=0ull; }
    const float* hp = hs + mg*HP + kbase;
    const float* w0 = wr + cjp*WP;
    #pragma unroll 4
    for (int k = 0; k < 64; k += 2){
        unsigned long long wv0 = *(const unsigned long long*)(w0 + k);
        unsigned long long wv1 = *(const unsigned long long*)(w0 + 4*WP + k);
        unsigned long long wv2 = *(const unsigned long long*)(w0 + 8*WP + k);
        #pragma unroll
        for (int i = 0; i < 8; i++){
            unsigned long long a = *(const unsigned long long*)(hp + i*8*HP + k);
            FMA2(acc[i][0], a, wv0);
            FMA2(acc[i][1], a, wv1);
            FMA2(acc[i][2], a, wv2);
        }
    }
    #pragma unroll
    for (int i = 0; i < 8; i++){
        int m = mg + 8*i;
        #pragma unroll
        for (int g = 0; g < 3; g++){
            float lo, hi; UNPK(lo, hi, acc[i][g]);
            pb[(g*4 + cjp)*64 + m] = lo + hi;
        }
    }
}
__device__ __forceinline__ float psum(const float* __restrict__ pbuf, int r, int b){
    float s = 0.f;
    #pragma unroll
    for (int w = 0; w < 8; w++) s += pbuf[(w*12 + r)*64 + b];
    return s;
}

__global__ __launch_bounds__(256,1) void scan_k(
    const float* __restrict__ Whh, const float* __restrict__ bhh,
    const float* __restrict__ bih, const float* __restrict__ gi_all,
    const float* __restrict__ h0, float* __restrict__ chain, int steps)
{
    extern __shared__ float sm[];
    float* hs = sm;
    float* wst = sm + 64*HP;
    float* pbuf = wst + 8*12*WP;
    const int tid = threadIdx.x, w = tid >> 5;
    const int c0 = blockIdx.x*4, kbase = w*64;
    float* wstw = wst + w*12*WP;
    float* pbw = pbuf + w*PBS;
    const int b = tid & 63, cj = tid >> 6;
    const int c = c0 + cj;
    unsigned gen = 0;

    stage_w(Whh, NH, c0, kbase, wstw);
    const float bhr = bhh[c], bhz = bhh[NH+c], bhn = bhh[2*NH+c];

    for (int step = 0; step < steps; step++){
        const float* hin = step ? (chain + (size_t)(step-1)*BHSZ) : h0;
        float* hout = chain + (size_t)step*BHSZ;
        const float* gp = gi_all ? (gi_all + ((size_t)step*NB + b)*NG) : bih;
        float gir = gp[c], giz = gp[NH+c], gin = gp[2*NH+c];
        stage_h(hin, hs);
        __syncthreads();
        micro_mm(hs, wstw, pbw, kbase);
        __syncthreads();
        {
            float ghr = bhr + psum(pbuf, cj, b);
            float ghz = bhz + psum(pbuf, 4+cj, b);
            float ghn = bhn + psum(pbuf, 8+cj, b);
            float r  = sigm(gir + ghr);
            float z  = sigm(giz + ghz);
            float nn = tanhf(gin + r*ghn);
            hout[b*NH + c] = (1.f - z)*nn + z*hs[b*HP + c];
        }
        gridbar(gen);
    }
}

// ================= batched decoder gates =================
__global__ void dec_gates_k(const float* __restrict__ gi_all, const float* __restrict__ gh_all,
                            const float* __restrict__ hv_all, const float* __restrict__ Wc,
                            const int* __restrict__ y, float* __restrict__ hc_all)
{
    int idx = blockIdx.x*blockDim.x + threadIdx.x;
    if (idx >= (NL-1)*BHSZ) return;
    int s = idx / BHSZ, r = idx % BHSZ;
    int b = r >> 9, c = r & 511;
    size_t m = (size_t)s*NB + b;
    const float* gi = gi_all + m*NG;
    const float* gh = gh_all + m*NG;
    int yb = y[s*NB + b];
    float gir = gi[c]      + Wc[(size_t)c*(NH+NWD)        + NH + yb];
    float giz = gi[NH+c]   + Wc[(size_t)(NH+c)*(NH+NWD)   + NH + yb];
    float gin = gi[2*NH+c] + Wc[(size_t)(2*NH+c)*(NH+NWD) + NH + yb];
    float rr = sigm(gir + gh[c]);
    float zz = sigm(giz + gh[NH+c]);
    float nn = tanhf(gin + rr*gh[2*NH+c]);
    hc_all[(size_t)s*BHSZ + r] = (1.f - zz)*nn + zz*hv_all[(size_t)s*BHSZ + r];
}

// ================= misc =================
__global__ void init_k(float* __restrict__ out){
    int idx = blockIdx.x*blockDim.x + threadIdx.x;
    if (idx < NB*NWD){
        int b = idx / NWD, n = idx % NWD;
        out[(size_t)b*OUTROW + n] = (b == 0 && n == 1) ? 1.f : 0.f;
    }
    if (idx < BHSZ) g_h0[idx] = 0.f;
    if (idx == 0) g_barrier = 0u;
}
__global__ void bar0_k(){ if (threadIdx.x == 0) g_barrier = 0u; }
__global__ void loss1_k(const float* __restrict__ out, const int* __restrict__ y,
                        float* __restrict__ part){
    int b = blockIdx.x;
    const float* row = out + (size_t)b*OUTROW + (size_t)(NL-1)*NWD;
    __shared__ float red[256];
    float m = -1e30f;
    for (int i = threadIdx.x; i < NWD; i += 256) m = fmaxf(m, row[i]);
    red[threadIdx.x] = m; __syncthreads();
    for (int s = 128; s > 0; s >>= 1){ if (threadIdx.x < s) red[threadIdx.x] = fmaxf(red[threadIdx.x], red[threadIdx.x+s]); __syncthreads(); }
    m = red[0]; __syncthreads();
    float sum = 0.f;
    for (int i = threadIdx.x; i < NWD; i += 256) sum += expf(row[i] - m);
    red[threadIdx.x] = sum; __syncthreads();
    for (int s = 128; s > 0; s >>= 1){ if (threadIdx.x < s) red[threadIdx.x] += red[threadIdx.x+s]; __syncthreads(); }
    if (threadIdx.x == 0){
        int t = y[(NL-1)*NB + b];
        part[b] = -(row[t] - m - logf(red[0]));
    }
}
__global__ void loss2_k(const float* __restrict__ part, float* __restrict__ out){
    if (threadIdx.x == 0){
        float s = 0.f;
        for (int b = 0; b < NB; b++) s += part[b];
        out[(size_t)NB*NL*NWD] = s/(float)NB;
    }
}

extern "C" void kernel_launch(void* const* d_in, const int* in_sizes, int n_in,
                              void* d_out, int out_size){
    const float* x     = (const float*)d_in[0];
    const int*   y     = (const int*)  d_in[1];
    const float* Wih_v = (const float*)d_in[2];
    const float* Whh_v = (const float*)d_in[3];
    const float* bih_v = (const float*)d_in[4];
    const float* bhh_v = (const float*)d_in[5];
    const float* Wih_c = (const float*)d_in[6];
    const float* Whh_c = (const float*)d_in[7];
    const float* bih_c = (const float*)d_in[8];
    const float* bhh_c = (const float*)d_in[9];
    const float* Wout  = (const float*)d_in[10];
    const float* bout  = (const float*)d_in[11];
    float* out = (float*)d_out;

    float *gi, *gic, *enc, *h0, *hvall, *hcall, *lp;
    cudaGetSymbolAddress((void**)&gi,    g_gi);
    cudaGetSymbolAddress((void**)&gic,   g_gic);
    cudaGetSymbolAddress((void**)&enc,   g_enc);
    cudaGetSymbolAddress((void**)&h0,    g_h0);
    cudaGetSymbolAddress((void**)&hvall, g_hvall);
    cudaGetSymbolAddress((void**)&hcall, g_hcall);
    cudaGetSymbolAddress((void**)&lp,    g_lpart);

    cudaFuncSetAttribute(scan_k, cudaFuncAttributeMaxDynamicSharedMemorySize, SMEM_BYTES);

    init_k<<<(NB*NWD + 255)/256, 256>>>(out);

    // gi_v = x @ Wih_v^T + bih_v   (5120 x 1536 x 4096) -> g_gi
    gemm2_k<<<dim3(NG/128, NT*NB/128), 256>>>(x, Wih_v, bih_v, gi,
        NT*NB, NG, NF, NF, NF, NG, 1, 0);

    // encoder-v: chain = g_enc (== enc_out)
    scan_k<<<128, 256, SMEM_BYTES>>>(Whh_v, bhh_v, nullptr, gi, h0, enc, NT);

    // gi_c = enc_out @ Wih_c[:, :H]^T + bih_c -> g_gic
    gemm2_k<<<dim3(NG/128, NT*NB/128), 256>>>(enc, Wih_c, bih_c, gic,
        NT*NB, NG, NH, NH, NH+NWD, NG, 0, 0);

    bar0_k<<<1, 32>>>();
    // encoder-c: chain = g_gi (gi_v dead)
    scan_k<<<128, 256, SMEM_BYTES>>>(Whh_c, bhh_c, nullptr, gic, h0, gi, NT);

    bar0_k<<<1, 32>>>();
    // decoder h_v chain: h0 = chain_c[79], 31 steps, gi = bih_v
    scan_k<<<128, 256, SMEM_BYTES>>>(Whh_v, bhh_v, bih_v, nullptr,
        gi + (size_t)(NT-1)*BHSZ, hvall, NL-1);

    // batched decoder (gh -> g_gi: 7.86M floats; g_enc is too small for 2048x1536!)
    gemm2_k<<<dim3(NG/128, 16), 256>>>(hvall, Wih_c, bih_c, gic,
        2048, NG, NH, NH, NH+NWD, NG, 0, 0);
    gemm2_k<<<dim3(NG/128, 16), 256>>>(hvall, Whh_c, bhh_c, gi,
        2048, NG, NH, NH, NH, NG, 0, 0);
    dec_gates_k<<<((NL-1)*BHSZ + 255)/256, 256>>>(gic, gi, hvall, Wih_c, y, hcall);
    // logits = hc_all @ Wout^T + bout -> probs[:, s+1, :]
    gemm2_k<<<dim3((NWD + 127)/128, 16), 256>>>(hcall, Wout, bout, out,
        (NL-1)*NB, NWD, NH, NH, NH, 0, 0, 1);

    loss1_k<<<NB, 256>>>(out, y, lp);
    loss2_k<<<1, 32>>>(lp, out);
}

// round 8
// speedup vs baseline: 1.3130x; 1.1977x over previous
#include <cuda_runtime.h>
#include <math.h>
#include <stdint.h>
#include <stddef.h>

#define NB 64
#define NT 80
#define NF 4096
#define NH 512
#define NG 1536
#define NWD 6000
#define NL 32
#define BHSZ (NB*NH)
#define OUTROW ((size_t)NL*NWD)

#define HP 516
#define WP 66
#define PBS (12*64)
#define SMEM_FLOATS (64*HP + 8*12*WP + 8*PBS)
#define SMEM_BYTES (SMEM_FLOATS*4)

__device__ float g_gi [NT*NB*NG];     // gi_v -> enc-c chain -> dec gh
__device__ float g_gic[NT*NB*NG];     // gi_c -> dec gi
__device__ float g_enc[NT*NB*NH];     // enc-v chain (= enc_out) ONLY
__device__ float g_h0 [BHSZ];         // zeros
__device__ float g_hvall[32*BHSZ];
__device__ float g_hcall[32*BHSZ];
__device__ float g_lpart[NB];
__device__ unsigned g_barrier;

#define FMA2(d,a,b) asm("fma.rn.f32x2 %0, %1, %2, %0;" : "+l"(d) : "l"(a), "l"(b))
#define DUP(d,v)    asm("mov.b64 %0,{%1,%1};" : "=l"(d) : "f"(v))
#define UNPK(lo,hi,d) asm("mov.b64 {%0,%1}, %2;" : "=f"(lo), "=f"(hi) : "l"(d))
__device__ __forceinline__ float sigm(float x){ return 1.f/(1.f+expf(-x)); }

__device__ __forceinline__ void gridbar(unsigned& gen){
    __syncthreads();
    if (threadIdx.x == 0){
        gen += gridDim.x;
        asm volatile("red.release.gpu.global.add.u32 [%0], %1;" :: "l"(&g_barrier), "r"(1u) : "memory");
        unsigned v;
        do {
            __nanosleep(20);
            asm volatile("ld.acquire.gpu.global.u32 %0, [%1];" : "=r"(v) : "l"(&g_barrier) : "memory");
        } while (v < gen);
    }
    __syncthreads();
}

// ====== proven 64x64 GEMM (R3: 19.7 TMAC/s): C[m,n] = sum_k A[m,k]*B[n,k] + bias[n] ======
// amode=1: A row m -> x[(m&63)*NT + (m>>6)]
// cmode=1: C row m -> out[(m&63)*OUTROW + ((m>>6)+1)*NWD]  (logits -> probs)
__global__ __launch_bounds__(128) void gemm_k(
    const float* __restrict__ A, const float* __restrict__ B,
    const float* __restrict__ bias, float* __restrict__ C,
    int N, int K, int lda, int ldb, int ldc, int amode, int cmode)
{
    __shared__ __align__(16) float As[16][64];
    __shared__ __align__(16) float Bs[16][72];
    const int tid = threadIdx.x;
    const int bn0 = blockIdx.x*64;
    const int bm0 = blockIdx.y*64;
    const int lrow = tid >> 1, lk = (tid & 1)*8;
    const int am = bm0 + lrow;
    const float* arow;
    if (amode == 1){ int b_ = am & 63, t_ = am >> 6; arow = A + ((size_t)b_*NT + t_)*(size_t)lda; }
    else arow = A + (size_t)am*(size_t)lda;
    const float* brow = B + (size_t)(bn0 + lrow)*(size_t)ldb;
    const bool bval = (bn0 + lrow) < N;
    const int ty = tid >> 4, tx = tid & 15;

    unsigned long long acc[4][4];
    #pragma unroll
    for (int i = 0; i < 4; i++)
        #pragma unroll
        for (int j = 0; j < 4; j++) acc[i][j] = 0ull;

    for (int kk = 0; kk < K; kk += 16){
        float4 a0 = *(const float4*)(arow + kk + lk);
        float4 a1 = *(const float4*)(arow + kk + lk + 4);
        float4 b0 = make_float4(0.f,0.f,0.f,0.f), b1 = make_float4(0.f,0.f,0.f,0.f);
        if (bval){ b0 = *(const float4*)(brow + kk + lk); b1 = *(const float4*)(brow + kk + lk + 4); }
        As[lk+0][lrow]=a0.x; As[lk+1][lrow]=a0.y; As[lk+2][lrow]=a0.z; As[lk+3][lrow]=a0.w;
        As[lk+4][lrow]=a1.x; As[lk+5][lrow]=a1.y; As[lk+6][lrow]=a1.z; As[lk+7][lrow]=a1.w;
        Bs[lk+0][lrow]=b0.x; Bs[lk+1][lrow]=b0.y; Bs[lk+2][lrow]=b0.z; Bs[lk+3][lrow]=b0.w;
        Bs[lk+4][lrow]=b1.x; Bs[lk+5][lrow]=b1.y; Bs[lk+6][lrow]=b1.z; Bs[lk+7][lrow]=b1.w;
        __syncthreads();
        #pragma unroll
        for (int k = 0; k < 16; k++){
            const float* ap = &As[k][ty*8];
            unsigned long long av[4];
            av[0] = *(const unsigned long long*)(ap+0);
            av[1] = *(const unsigned long long*)(ap+2);
            av[2] = *(const unsigned long long*)(ap+4);
            av[3] = *(const unsigned long long*)(ap+6);
            float4 bv = *(const float4*)&Bs[k][tx*4];
            unsigned long long bd0,bd1,bd2,bd3;
            DUP(bd0, bv.x); DUP(bd1, bv.y); DUP(bd2, bv.z); DUP(bd3, bv.w);
            #pragma unroll
            for (int i = 0; i < 4; i++){
                FMA2(acc[i][0], av[i], bd0);
                FMA2(acc[i][1], av[i], bd1);
                FMA2(acc[i][2], av[i], bd2);
                FMA2(acc[i][3], av[i], bd3);
            }
        }
        __syncthreads();
    }
    #pragma unroll
    for (int i = 0; i < 4; i++){
        int m = bm0 + ty*8 + 2*i;
        float *r0, *r1;
        if (cmode == 1){
            r0 = C + (size_t)(m & 63)*OUTROW + (size_t)((m >> 6) + 1)*NWD;
            r1 = C + (size_t)((m+1) & 63)*OUTROW + (size_t)(((m+1) >> 6) + 1)*NWD;
        } else {
            r0 = C + (size_t)m*ldc;
            r1 = r0 + ldc;
        }
        #pragma unroll
        for (int j = 0; j < 4; j++){
            int n = bn0 + tx*4 + j;
            if (n < N){
                float lo, hi; UNPK(lo, hi, acc[i][j]);
                float bb = bias[n];
                r0[n] = lo + bb;
                r1[n] = hi + bb;
            }
        }
    }
}

// ================= persistent scan =================
__device__ __forceinline__ void stage_h(const float* __restrict__ src, float* __restrict__ hs){
    int t = threadIdx.x;
    #pragma unroll
    for (int i = 0; i < 32; i++){
        int lin = (i*256 + t)*4;
        int b = lin >> 9, k = lin & 511;
        *(float4*)(hs + b*HP + k) = *(const float4*)(src + lin);
    }
}
__device__ __forceinline__ void stage_w(const float* __restrict__ W, int ld, int base,
                                        int kbase, float* __restrict__ dst){
    int lane = threadIdx.x & 31;
    #pragma unroll
    for (int r = 0; r < 12; r++){
        int row = (r>>2)*NH + base + (r&3);
        float2 v = *(const float2*)(W + (size_t)row*ld + kbase + 2*lane);
        *(float2*)(dst + r*WP + 2*lane) = v;
    }
    __syncwarp();
}
__device__ __forceinline__ void micro_mm(const float* __restrict__ hs,
                                         const float* __restrict__ wr,
                                         float* __restrict__ pb, int kbase){
    int lane = threadIdx.x & 31;
    int cjp = lane & 3, mg = lane >> 2;
    unsigned long long acc[8][3];
    #pragma unroll
    for (int i = 0; i < 8; i++){ acc[i][0]=0ull; acc[i][1]=0ull; acc[i][2]=0ull; }
    const float* hp = hs + mg*HP + kbase;
    const float* w0 = wr + cjp*WP;
    #pragma unroll 4
    for (int k = 0; k < 64; k += 2){
        unsigned long long wv0 = *(const unsigned long long*)(w0 + k);
        unsigned long long wv1 = *(const unsigned long long*)(w0 + 4*WP + k);
        unsigned long long wv2 = *(const unsigned long long*)(w0 + 8*WP + k);
        #pragma unroll
        for (int i = 0; i < 8; i++){
            unsigned long long a = *(const unsigned long long*)(hp + i*8*HP + k);
            FMA2(acc[i][0], a, wv0);
            FMA2(acc[i][1], a, wv1);
            FMA2(acc[i][2], a, wv2);
        }
    }
    #pragma unroll
    for (int i = 0; i < 8; i++){
        int m = mg + 8*i;
        #pragma unroll
        for (int g = 0; g < 3; g++){
            float lo, hi; UNPK(lo, hi, acc[i][g]);
            pb[(g*4 + cjp)*64 + m] = lo + hi;
        }
    }
}
__device__ __forceinline__ float psum(const float* __restrict__ pbuf, int r, int b){
    float s = 0.f;
    #pragma unroll
    for (int w = 0; w < 8; w++) s += pbuf[(w*12 + r)*64 + b];
    return s;
}

__global__ __launch_bounds__(256,1) void scan_k(
    const float* __restrict__ Whh, const float* __restrict__ bhh,
    const float* __restrict__ bih, const float* __restrict__ gi_all,
    const float* __restrict__ h0, float* __restrict__ chain, int steps)
{
    extern __shared__ float sm[];
    float* hs = sm;
    float* wst = sm + 64*HP;
    float* pbuf = wst + 8*12*WP;
    const int tid = threadIdx.x, w = tid >> 5;
    const int c0 = blockIdx.x*4, kbase = w*64;
    float* wstw = wst + w*12*WP;
    float* pbw = pbuf + w*PBS;
    const int b = tid & 63, cj = tid >> 6;
    const int c = c0 + cj;
    unsigned gen = 0;

    stage_w(Whh, NH, c0, kbase, wstw);
    const float bhr = bhh[c], bhz = bhh[NH+c], bhn = bhh[2*NH+c];

    for (int step = 0; step < steps; step++){
        const float* hin = step ? (chain + (size_t)(step-1)*BHSZ) : h0;
        float* hout = chain + (size_t)step*BHSZ;
        const float* gp = gi_all ? (gi_all + ((size_t)step*NB + b)*NG) : bih;
        float gir = gp[c], giz = gp[NH+c], gin = gp[2*NH+c];
        stage_h(hin, hs);
        __syncthreads();
        micro_mm(hs, wstw, pbw, kbase);
        __syncthreads();
        {
            float ghr = bhr + psum(pbuf, cj, b);
            float ghz = bhz + psum(pbuf, 4+cj, b);
            float ghn = bhn + psum(pbuf, 8+cj, b);
            float r  = sigm(gir + ghr);
            float z  = sigm(giz + ghz);
            float nn = tanhf(gin + r*ghn);
            hout[b*NH + c] = (1.f - z)*nn + z*hs[b*HP + c];
        }
        gridbar(gen);
    }
}

// ================= batched decoder gates =================
__global__ void dec_gates_k(const float* __restrict__ gi_all, const float* __restrict__ gh_all,
                            const float* __restrict__ hv_all, const float* __restrict__ Wc,
                            const int* __restrict__ y, float* __restrict__ hc_all)
{
    int idx = blockIdx.x*blockDim.x + threadIdx.x;
    if (idx >= (NL-1)*BHSZ) return;
    int s = idx / BHSZ, r = idx % BHSZ;
    int b = r >> 9, c = r & 511;
    size_t m = (size_t)s*NB + b;
    const float* gi = gi_all + m*NG;
    const float* gh = gh_all + m*NG;
    int yb = y[s*NB + b];
    float gir = gi[c]      + Wc[(size_t)c*(NH+NWD)        + NH + yb];
    float giz = gi[NH+c]   + Wc[(size_t)(NH+c)*(NH+NWD)   + NH + yb];
    float gin = gi[2*NH+c] + Wc[(size_t)(2*NH+c)*(NH+NWD) + NH + yb];
    float rr = sigm(gir + gh[c]);
    float zz = sigm(giz + gh[NH+c]);
    float nn = tanhf(gin + rr*gh[2*NH+c]);
    hc_all[(size_t)s*BHSZ + r] = (1.f - zz)*nn + zz*hv_all[(size_t)s*BHSZ + r];
}

// ================= misc =================
__global__ void init_k(float* __restrict__ out){
    int idx = blockIdx.x*blockDim.x + threadIdx.x;
    if (idx < NB*NWD){
        int b = idx / NWD, n = idx % NWD;
        out[(size_t)b*OUTROW + n] = (b == 0 && n == 1) ? 1.f : 0.f;
    }
    if (idx < BHSZ) g_h0[idx] = 0.f;
    if (idx == 0) g_barrier = 0u;
}
__global__ void bar0_k(){ if (threadIdx.x == 0) g_barrier = 0u; }
__global__ void loss1_k(const float* __restrict__ out, const int* __restrict__ y,
                        float* __restrict__ part){
    int b = blockIdx.x;
    const float* row = out + (size_t)b*OUTROW + (size_t)(NL-1)*NWD;
    __shared__ float red[256];
    float m = -1e30f;
    for (int i = threadIdx.x; i < NWD; i += 256) m = fmaxf(m, row[i]);
    red[threadIdx.x] = m; __syncthreads();
    for (int s = 128; s > 0; s >>= 1){ if (threadIdx.x < s) red[threadIdx.x] = fmaxf(red[threadIdx.x], red[threadIdx.x+s]); __syncthreads(); }
    m = red[0]; __syncthreads();
    float sum = 0.f;
    for (int i = threadIdx.x; i < NWD; i += 256) sum += expf(row[i] - m);
    red[threadIdx.x] = sum; __syncthreads();
    for (int s = 128; s > 0; s >>= 1){ if (threadIdx.x < s) red[threadIdx.x] += red[threadIdx.x+s]; __syncthreads(); }
    if (threadIdx.x == 0){
        int t = y[(NL-1)*NB + b];
        part[b] = -(row[t] - m - logf(red[0]));
    }
}
__global__ void loss2_k(const float* __restrict__ part, float* __restrict__ out){
    if (threadIdx.x == 0){
        float s = 0.f;
        for (int b = 0; b < NB; b++) s += part[b];
        out[(size_t)NB*NL*NWD] = s/(float)NB;
    }
}

extern "C" void kernel_launch(void* const* d_in, const int* in_sizes, int n_in,
                              void* d_out, int out_size){
    const float* x     = (const float*)d_in[0];
    const int*   y     = (const int*)  d_in[1];
    const float* Wih_v = (const float*)d_in[2];
    const float* Whh_v = (const float*)d_in[3];
    const float* bih_v = (const float*)d_in[4];
    const float* bhh_v = (const float*)d_in[5];
    const float* Wih_c = (const float*)d_in[6];
    const float* Whh_c = (const float*)d_in[7];
    const float* bih_c = (const float*)d_in[8];
    const float* bhh_c = (const float*)d_in[9];
    const float* Wout  = (const float*)d_in[10];
    const float* bout  = (const float*)d_in[11];
    float* out = (float*)d_out;

    float *gi, *gic, *enc, *h0, *hvall, *hcall, *lp;
    cudaGetSymbolAddress((void**)&gi,    g_gi);
    cudaGetSymbolAddress((void**)&gic,   g_gic);
    cudaGetSymbolAddress((void**)&enc,   g_enc);
    cudaGetSymbolAddress((void**)&h0,    g_h0);
    cudaGetSymbolAddress((void**)&hvall, g_hvall);
    cudaGetSymbolAddress((void**)&hcall, g_hcall);
    cudaGetSymbolAddress((void**)&lp,    g_lpart);

    cudaFuncSetAttribute(scan_k, cudaFuncAttributeMaxDynamicSharedMemorySize, SMEM_BYTES);

    init_k<<<(NB*NWD + 255)/256, 256>>>(out);

    // gi_v = x @ Wih_v^T + bih_v   (5120 x 1536 x 4096) -> g_gi
    gemm_k<<<dim3(NG/64, NT*NB/64), 128>>>(x, Wih_v, bih_v, gi,
        NG, NF, NF, NF, NG, 1, 0);

    // encoder-v: chain = g_enc (== enc_out)
    scan_k<<<128, 256, SMEM_BYTES>>>(Whh_v, bhh_v, nullptr, gi, h0, enc, NT);

    // gi_c = enc_out @ Wih_c[:, :H]^T + bih_c -> g_gic
    gemm_k<<<dim3(NG/64, NT*NB/64), 128>>>(enc, Wih_c, bih_c, gic,
        NG, NH, NH, NH+NWD, NG, 0, 0);

    bar0_k<<<1, 32>>>();
    // encoder-c: chain = g_gi (gi_v dead)
    scan_k<<<128, 256, SMEM_BYTES>>>(Whh_c, bhh_c, nullptr, gic, h0, gi, NT);

    bar0_k<<<1, 32>>>();
    // decoder h_v chain: h0 = chain_c[79], 31 steps, gi = bih_v
    scan_k<<<128, 256, SMEM_BYTES>>>(Whh_v, bhh_v, bih_v, nullptr,
        gi + (size_t)(NT-1)*BHSZ, hvall, NL-1);

    // batched decoder (gh -> g_gi: 7.86M floats; g_enc too small for 2048x1536)
    gemm_k<<<dim3(NG/64, 2048/64), 128>>>(hvall, Wih_c, bih_c, gic,
        NG, NH, NH, NH+NWD, NG, 0, 0);
    gemm_k<<<dim3(NG/64, 2048/64), 128>>>(hvall, Whh_c, bhh_c, gi,
        NG, NH, NH, NH, NG, 0, 0);
    dec_gates_k<<<((NL-1)*BHSZ + 255)/256, 256>>>(gic, gi, hvall, Wih_c, y, hcall);
    // logits = hc_all @ Wout^T + bout -> probs[:, s+1, :]   (1984 x 6000 x 512)
    gemm_k<<<dim3((NWD + 63)/64, (NL-1)*NB/64), 128>>>(hcall, Wout, bout, out,
        NWD, NH, NH, NH, 0, 0, 1);

    loss1_k<<<NB, 256>>>(out, y, lp);
    loss2_k<<<1, 32>>>(lp, out);
}

// round 10
// speedup vs baseline: 1.6257x; 1.2381x over previous
#include <cuda_runtime.h>
#include <cuda_bf16.h>
#include <math.h>
#include <stdint.h>
#include <stddef.h>

#define NB 64
#define NT 80
#define NF 4096
#define NH 512
#define NG 1536
#define NWD 6000
#define NL 32
#define BHSZ (NB*NH)
#define OUTROW ((size_t)NL*NWD)

#define HP 516
#define WP 66
#define PBS (12*64)
#define SMEM_FLOATS (64*HP + 8*12*WP + 8*PBS)
#define SMEM_BYTES (SMEM_FLOATS*4)

__device__ float g_gi [NT*NB*NG];
__device__ float g_gic[NT*NB*NG];
__device__ float g_enc[NT*NB*NH];
__device__ float g_h0 [BHSZ];
__device__ float g_hvall[32*BHSZ];
__device__ float g_hcall[32*BHSZ];
__device__ float g_lpart[NB];
__device__ unsigned g_barrier;
__device__ __nv_bfloat16 g_xh[(size_t)NT*NB*NF];
__device__ __nv_bfloat16 g_xl[(size_t)NT*NB*NF];
__device__ __nv_bfloat16 g_wh[(size_t)NG*NF];
__device__ __nv_bfloat16 g_wl[(size_t)NG*NF];

#define FMA2(d,a,b) asm("fma.rn.f32x2 %0, %1, %2, %0;" : "+l"(d) : "l"(a), "l"(b))
#define DUP(d,v)    asm("mov.b64 %0,{%1,%1};" : "=l"(d) : "f"(v))
#define UNPK(lo,hi,d) asm("mov.b64 {%0,%1}, %2;" : "=f"(lo), "=f"(hi) : "l"(d))
__device__ __forceinline__ float sigm(float x){ return 1.f/(1.f+expf(-x)); }

__device__ __forceinline__ void gridbar(unsigned& gen){
    __syncthreads();
    if (threadIdx.x == 0){
        gen += gridDim.x;
        asm volatile("red.release.gpu.global.add.u32 [%0], %1;" :: "l"(&g_barrier), "r"(1u) : "memory");
        unsigned v;
        do {
            __nanosleep(20);
            asm volatile("ld.acquire.gpu.global.u32 %0, [%1];" : "=r"(v) : "l"(&g_barrier) : "memory");
        } while (v < gen);
    }
    __syncthreads();
}

__device__ __forceinline__ uint32_t smem_u32(const void* p){
    uint32_t a;
    asm("{ .reg .u64 t; cvta.to.shared.u64 t, %1; cvt.u32.u64 %0, t; }" : "=r"(a) : "l"(p));
    return a;
}
#define LDSM4(r0,r1,r2,r3,addr) \
    asm volatile("ldmatrix.sync.aligned.m8n8.x4.shared.b16 {%0,%1,%2,%3}, [%4];" \
        : "=r"(r0),"=r"(r1),"=r"(r2),"=r"(r3) : "r"(addr))
#define MMA16816(d,a0,a1,a2,a3,b0,b1) \
    asm volatile("mma.sync.aligned.m16n8k16.row.col.f32.bf16.bf16.f32 " \
        "{%0,%1,%2,%3}, {%4,%5,%6,%7}, {%8,%9}, {%0,%1,%2,%3};" \
        : "+f"((d)[0]),"+f"((d)[1]),"+f"((d)[2]),"+f"((d)[3]) \
        : "r"(a0),"r"(a1),"r"(a2),"r"(a3), "r"(b0),"r"(b1))

// ======== tensor-pipe GEMM for gi_v: C[5120,1536] = X @ W^T + bias ========
// 3-phase bf16 split: (xh,wh),(xh,wl),(xl,wh). 128x128 tile, BK=32, 8 warps (2x4).
#define SPAD 40
__global__ __launch_bounds__(256, 2) void mmagemm_k(
    const __nv_bfloat16* __restrict__ xh, const __nv_bfloat16* __restrict__ xl,
    const __nv_bfloat16* __restrict__ wh, const __nv_bfloat16* __restrict__ wl,
    const float* __restrict__ bias, float* __restrict__ C)
{
    __shared__ __align__(16) __nv_bfloat16 As[128][SPAD];
    __shared__ __align__(16) __nv_bfloat16 Bs[128][SPAD];
    const int tid = threadIdx.x, wid = tid >> 5, lane = tid & 31;
    const int bn0 = blockIdx.x*128, bm0 = blockIdx.y*128;
    const int wm = (wid >> 2)*64, wn = (wid & 3)*32;
    const uint32_t asmb = smem_u32(&As[0][0]);
    const uint32_t bsmb = smem_u32(&Bs[0][0]);

    float acc[4][4][4];
    #pragma unroll
    for (int i = 0; i < 4; i++)
        #pragma unroll
        for (int a = 0; a < 4; a++){ acc[i][a][0]=0.f; acc[i][a][1]=0.f; acc[i][a][2]=0.f; acc[i][a][3]=0.f; }

    const int srow = tid >> 2, sseg = (tid & 3)*8;
    // precompute ldmatrix element offsets (lane-dependent parts)
    const int a_r = lane & 15, a_c8 = (lane >> 4)*8;
    const int b_tile = lane >> 3, b_r = lane & 7;
    const int b_nrow_off = (b_tile >> 1)*8 + b_r;
    const int b_kcol_off = (b_tile & 1)*8;

    for (int c = 0; c < 384; c++){
        const int ph = c >> 7, kin = (c & 127) << 5;
        const __nv_bfloat16* sA = (ph < 2) ? xh : xl;
        const __nv_bfloat16* sB = (ph == 1) ? wl : wh;
        uint4 ra0 = *(const uint4*)(sA + (size_t)(bm0 + srow   )*NF + kin + sseg);
        uint4 ra1 = *(const uint4*)(sA + (size_t)(bm0 + srow+64)*NF + kin + sseg);
        uint4 rb0 = *(const uint4*)(sB + (size_t)(bn0 + srow   )*NF + kin + sseg);
        uint4 rb1 = *(const uint4*)(sB + (size_t)(bn0 + srow+64)*NF + kin + sseg);
        __syncthreads();
        *(uint4*)&As[srow   ][sseg] = ra0;
        *(uint4*)&As[srow+64][sseg] = ra1;
        *(uint4*)&Bs[srow   ][sseg] = rb0;
        *(uint4*)&Bs[srow+64][sseg] = rb1;
        __syncthreads();
        #pragma unroll
        for (int kk = 0; kk < 2; kk++){
            uint32_t af[4][4];
            #pragma unroll
            for (int i = 0; i < 4; i++){
                uint32_t addr = asmb + (uint32_t)(((wm + i*16 + a_r)*SPAD + kk*16 + a_c8)*2);
                LDSM4(af[i][0], af[i][1], af[i][2], af[i][3], addr);
            }
            uint32_t bf[2][4];
            #pragma unroll
            for (int j = 0; j < 2; j++){
                uint32_t addr = bsmb + (uint32_t)(((wn + j*16 + b_nrow_off)*SPAD + kk*16 + b_kcol_off)*2);
                LDSM4(bf[j][0], bf[j][1], bf[j][2], bf[j][3], addr);
            }
            #pragma unroll
            for (int i = 0; i < 4; i++)
                #pragma unroll
                for (int a = 0; a < 4; a++)
                    MMA16816(acc[i][a], af[i][0], af[i][1], af[i][2], af[i][3],
                             bf[a>>1][(a&1)*2], bf[a>>1][(a&1)*2+1]);
        }
    }

    const int gr = lane >> 2, gc = (lane & 3)*2;
    #pragma unroll
    for (int i = 0; i < 4; i++){
        #pragma unroll
        for (int a = 0; a < 4; a++){
            int m = bm0 + wm + i*16 + gr;
            int n = bn0 + wn + a*8 + gc;
            float b0 = bias[n], b1 = bias[n+1];
            *(float2*)(C + (size_t)m*NG + n)     = make_float2(acc[i][a][0] + b0, acc[i][a][1] + b1);
            *(float2*)(C + (size_t)(m+8)*NG + n) = make_float2(acc[i][a][2] + b0, acc[i][a][3] + b1);
        }
    }
}

// ============ bf16 split conversions ============
__global__ void convx_k(const float* __restrict__ x, __nv_bfloat16* __restrict__ xh,
                        __nv_bfloat16* __restrict__ xl){
    size_t i4 = ((size_t)blockIdx.x*blockDim.x + threadIdx.x)*4;
    if (i4 >= (size_t)NT*NB*NF) return;
    int m = (int)(i4 >> 12), f = (int)(i4 & 4095);
    int b = m & 63, t = m >> 6;
    float4 v = *(const float4*)(x + ((size_t)b*NT + t)*NF + f);
    float vv[4] = {v.x, v.y, v.z, v.w};
    __nv_bfloat16 h[4], l[4];
    #pragma unroll
    for (int e = 0; e < 4; e++){
        h[e] = __float2bfloat16(vv[e]);
        l[e] = __float2bfloat16(vv[e] - __bfloat162float(h[e]));
    }
    *(uint2*)(xh + i4) = *(uint2*)h;
    *(uint2*)(xl + i4) = *(uint2*)l;
}
__global__ void convw_k(const float* __restrict__ w, __nv_bfloat16* __restrict__ wh,
                        __nv_bfloat16* __restrict__ wl){
    size_t i4 = ((size_t)blockIdx.x*blockDim.x + threadIdx.x)*4;
    if (i4 >= (size_t)NG*NF) return;
    float4 v = *(const float4*)(w + i4);
    float vv[4] = {v.x, v.y, v.z, v.w};
    __nv_bfloat16 h[4], l[4];
    #pragma unroll
    for (int e = 0; e < 4; e++){
        h[e] = __float2bfloat16(vv[e]);
        l[e] = __float2bfloat16(vv[e] - __bfloat162float(h[e]));
    }
    *(uint2*)(wh + i4) = *(uint2*)h;
    *(uint2*)(wl + i4) = *(uint2*)l;
}

// ====== proven 64x64 fp32 GEMM ======
__global__ __launch_bounds__(128) void gemm_k(
    const float* __restrict__ A, const float* __restrict__ B,
    const float* __restrict__ bias, float* __restrict__ C,
    int N, int K, int lda, int ldb, int ldc, int amode, int cmode)
{
    __shared__ __align__(16) float As[16][64];
    __shared__ __align__(16) float Bs[16][72];
    const int tid = threadIdx.x;
    const int bn0 = blockIdx.x*64;
    const int bm0 = blockIdx.y*64;
    const int lrow = tid >> 1, lk = (tid & 1)*8;
    const int am = bm0 + lrow;
    const float* arow;
    if (amode == 1){ int b_ = am & 63, t_ = am >> 6; arow = A + ((size_t)b_*NT + t_)*(size_t)lda; }
    else arow = A + (size_t)am*(size_t)lda;
    const float* brow = B + (size_t)(bn0 + lrow)*(size_t)ldb;
    const bool bval = (bn0 + lrow) < N;
    const int ty = tid >> 4, tx = tid & 15;

    unsigned long long acc[4][4];
    #pragma unroll
    for (int i = 0; i < 4; i++)
        #pragma unroll
        for (int j = 0; j < 4; j++) acc[i][j] = 0ull;

    for (int kk = 0; kk < K; kk += 16){
        float4 a0 = *(const float4*)(arow + kk + lk);
        float4 a1 = *(const float4*)(arow + kk + lk + 4);
        float4 b0 = make_float4(0.f,0.f,0.f,0.f), b1 = make_float4(0.f,0.f,0.f,0.f);
        if (bval){ b0 = *(const float4*)(brow + kk + lk); b1 = *(const float4*)(brow + kk + lk + 4); }
        As[lk+0][lrow]=a0.x; As[lk+1][lrow]=a0.y; As[lk+2][lrow]=a0.z; As[lk+3][lrow]=a0.w;
        As[lk+4][lrow]=a1.x; As[lk+5][lrow]=a1.y; As[lk+6][lrow]=a1.z; As[lk+7][lrow]=a1.w;
        Bs[lk+0][lrow]=b0.x; Bs[lk+1][lrow]=b0.y; Bs[lk+2][lrow]=b0.z; Bs[lk+3][lrow]=b0.w;
        Bs[lk+4][lrow]=b1.x; Bs[lk+5][lrow]=b1.y; Bs[lk+6][lrow]=b1.z; Bs[lk+7][lrow]=b1.w;
        __syncthreads();
        #pragma unroll
        for (int k = 0; k < 16; k++){
            const float* ap = &As[k][ty*8];
            unsigned long long av[4];
            av[0] = *(const unsigned long long*)(ap+0);
            av[1] = *(const unsigned long long*)(ap+2);
            av[2] = *(const unsigned long long*)(ap+4);
            av[3] = *(const unsigned long long*)(ap+6);
            float4 bv = *(const float4*)&Bs[k][tx*4];
            unsigned long long bd0,bd1,bd2,bd3;
            DUP(bd0, bv.x); DUP(bd1, bv.y); DUP(bd2, bv.z); DUP(bd3, bv.w);
            #pragma unroll
            for (int i = 0; i < 4; i++){
                FMA2(acc[i][0], av[i], bd0);
                FMA2(acc[i][1], av[i], bd1);
                FMA2(acc[i][2], av[i], bd2);
                FMA2(acc[i][3], av[i], bd3);
            }
        }
        __syncthreads();
    }
    #pragma unroll
    for (int i = 0; i < 4; i++){
        int m = bm0 + ty*8 + 2*i;
        float *r0, *r1;
        if (cmode == 1){
            r0 = C + (size_t)(m & 63)*OUTROW + (size_t)((m >> 6) + 1)*NWD;
            r1 = C + (size_t)((m+1) & 63)*OUTROW + (size_t)(((m+1) >> 6) + 1)*NWD;
        } else {
            r0 = C + (size_t)m*ldc;
            r1 = r0 + ldc;
        }
        #pragma unroll
        for (int j = 0; j < 4; j++){
            int n = bn0 + tx*4 + j;
            if (n < N){
                float lo, hi; UNPK(lo, hi, acc[i][j]);
                float bb = bias[n];
                r0[n] = lo + bb;
                r1[n] = hi + bb;
            }
        }
    }
}

// ================= persistent scan =================
__device__ __forceinline__ void stage_h(const float* __restrict__ src, float* __restrict__ hs){
    int t = threadIdx.x;
    #pragma unroll
    for (int i = 0; i < 32; i++){
        int lin = (i*256 + t)*4;
        int b = lin >> 9, k = lin & 511;
        *(float4*)(hs + b*HP + k) = *(const float4*)(src + lin);
    }
}
__device__ __forceinline__ void stage_w(const float* __restrict__ W, int ld, int base,
                                        int kbase, float* __restrict__ dst){
    int lane = threadIdx.x & 31;
    #pragma unroll
    for (int r = 0; r < 12; r++){
        int row = (r>>2)*NH + base + (r&3);
        float2 v = *(const float2*)(W + (size_t)row*ld + kbase + 2*lane);
        *(float2*)(dst + r*WP + 2*lane) = v;
    }
    __syncwarp();
}
__device__ __forceinline__ void micro_mm(const float* __restrict__ hs,
                                         const float* __restrict__ wr,
                                         float* __restrict__ pb, int kbase){
    int lane = threadIdx.x & 31;
    int cjp = lane & 3, mg = lane >> 2;
    unsigned long long acc[8][3];
    #pragma unroll
    for (int i = 0; i < 8; i++){ acc[i][0]=0ull; acc[i][1]=0ull; acc[i][2]=0ull; }
    const float* hp = hs + mg*HP + kbase;
    const float* w0 = wr + cjp*WP;
    #pragma unroll 4
    for (int k = 0; k < 64; k += 2){
        unsigned long long wv0 = *(const unsigned long long*)(w0 + k);
        unsigned long long wv1 = *(const unsigned long long*)(w0 + 4*WP + k);
        unsigned long long wv2 = *(const unsigned long long*)(w0 + 8*WP + k);
        #pragma unroll
        for (int i = 0; i < 8; i++){
            unsigned long long a = *(const unsigned long long*)(hp + i*8*HP + k);
            FMA2(acc[i][0], a, wv0);
            FMA2(acc[i][1], a, wv1);
            FMA2(acc[i][2], a, wv2);
        }
    }
    #pragma unroll
    for (int i = 0; i < 8; i++){
        int m = mg + 8*i;
        #pragma unroll
        for (int g = 0; g < 3; g++){
            float lo, hi; UNPK(lo, hi, acc[i][g]);
            pb[(g*4 + cjp)*64 + m] = lo + hi;
        }
    }
}
__device__ __forceinline__ float psum(const float* __restrict__ pbuf, int r, int b){
    float s = 0.f;
    #pragma unroll
    for (int w = 0; w < 8; w++) s += pbuf[(w*12 + r)*64 + b];
    return s;
}

__global__ __launch_bounds__(256,1) void scan_k(
    const float* __restrict__ Whh, const float* __restrict__ bhh,
    const float* __restrict__ bih, const float* __restrict__ gi_all,
    const float* __restrict__ h0, float* __restrict__ chain, int steps)
{
    extern __shared__ float sm[];
    float* hs = sm;
    float* wst = sm + 64*HP;
    float* pbuf = wst + 8*12*WP;
    const int tid = threadIdx.x, w = tid >> 5;
    const int c0 = blockIdx.x*4, kbase = w*64;
    float* wstw = wst + w*12*WP;
    float* pbw = pbuf + w*PBS;
    const int b = tid & 63, cj = tid >> 6;
    const int c = c0 + cj;
    unsigned gen = 0;

    stage_w(Whh, NH, c0, kbase, wstw);
    const float bhr = bhh[c], bhz = bhh[NH+c], bhn = bhh[2*NH+c];

    for (int step = 0; step < steps; step++){
        const float* hin = step ? (chain + (size_t)(step-1)*BHSZ) : h0;
        float* hout = chain + (size_t)step*BHSZ;
        const float* gp = gi_all ? (gi_all + ((size_t)step*NB + b)*NG) : bih;
        float gir = gp[c], giz = gp[NH+c], gin = gp[2*NH+c];
        stage_h(hin, hs);
        __syncthreads();
        micro_mm(hs, wstw, pbw, kbase);
        __syncthreads();
        {
            float ghr = bhr + psum(pbuf, cj, b);
            float ghz = bhz + psum(pbuf, 4+cj, b);
            float ghn = bhn + psum(pbuf, 8+cj, b);
            float r  = sigm(gir + ghr);
            float z  = sigm(giz + ghz);
            float nn = tanhf(gin + r*ghn);
            hout[b*NH + c] = (1.f - z)*nn + z*hs[b*HP + c];
        }
        gridbar(gen);
    }
}

// ================= batched decoder gates =================
__global__ void dec_gates_k(const float* __restrict__ gi_all, const float* __restrict__ gh_all,
                            const float* __restrict__ hv_all, const float* __restrict__ Wc,
                            const int* __restrict__ y, float* __restrict__ hc_all)
{
    int idx = blockIdx.x*blockDim.x + threadIdx.x;
    if (idx >= (NL-1)*BHSZ) return;
    int s = idx / BHSZ, r = idx % BHSZ;
    int b = r >> 9, c = r & 511;
    size_t m = (size_t)s*NB + b;
    const float* gi = gi_all + m*NG;
    const float* gh = gh_all + m*NG;
    int yb = y[s*NB + b];
    float gir = gi[c]      + Wc[(size_t)c*(NH+NWD)        + NH + yb];
    float giz = gi[NH+c]   + Wc[(size_t)(NH+c)*(NH+NWD)   + NH + yb];
    float gin = gi[2*NH+c] + Wc[(size_t)(2*NH+c)*(NH+NWD) + NH + yb];
    float rr = sigm(gir + gh[c]);
    float zz = sigm(giz + gh[NH+c]);
    float nn = tanhf(gin + rr*gh[2*NH+c]);
    hc_all[(size_t)s*BHSZ + r] = (1.f - zz)*nn + zz*hv_all[(size_t)s*BHSZ + r];
}

// ================= misc =================
__global__ void init_k(float* __restrict__ out){
    int idx = blockIdx.x*blockDim.x + threadIdx.x;
    if (idx < NB*NWD){
        int b = idx / NWD, n = idx % NWD;
        out[(size_t)b*OUTROW + n] = (b == 0 && n == 1) ? 1.f : 0.f;
    }
    if (idx < BHSZ) g_h0[idx] = 0.f;
    if (idx == 0) g_barrier = 0u;
}
__global__ void bar0_k(){ if (threadIdx.x == 0) g_barrier = 0u; }
__global__ void loss1_k(const float* __restrict__ out, const int* __restrict__ y,
                        float* __restrict__ part){
    int b = blockIdx.x;
    const float* row = out + (size_t)b*OUTROW + (size_t)(NL-1)*NWD;
    __shared__ float red[256];
    float m = -1e30f;
    for (int i = threadIdx.x; i < NWD; i += 256) m = fmaxf(m, row[i]);
    red[threadIdx.x] = m; __syncthreads();
    for (int s = 128; s > 0; s >>= 1){ if (threadIdx.x < s) red[threadIdx.x] = fmaxf(red[threadIdx.x], red[threadIdx.x+s]); __syncthreads(); }
    m = red[0]; __syncthreads();
    float sum = 0.f;
    for (int i = threadIdx.x; i < NWD; i += 256) sum += expf(row[i] - m);
    red[threadIdx.x] = sum; __syncthreads();
    for (int s = 128; s > 0; s >>= 1){ if (threadIdx.x < s) red[threadIdx.x] += red[threadIdx.x+s]; __syncthreads(); }
    if (threadIdx.x == 0){
        int t = y[(NL-1)*NB + b];
        part[b] = -(row[t] - m - logf(red[0]));
    }
}
__global__ void loss2_k(const float* __restrict__ part, float* __restrict__ out){
    if (threadIdx.x == 0){
        float s = 0.f;
        for (int b = 0; b < NB; b++) s += part[b];
        out[(size_t)NB*NL*NWD] = s/(float)NB;
    }
}

extern "C" void kernel_launch(void* const* d_in, const int* in_sizes, int n_in,
                              void* d_out, int out_size){
    const float* x     = (const float*)d_in[0];
    const int*   y     = (const int*)  d_in[1];
    const float* Wih_v = (const float*)d_in[2];
    const float* Whh_v = (const float*)d_in[3];
    const float* bih_v = (const float*)d_in[4];
    const float* bhh_v = (const float*)d_in[5];
    const float* Wih_c = (const float*)d_in[6];
    const float* Whh_c = (const float*)d_in[7];
    const float* bih_c = (const float*)d_in[8];
    const float* bhh_c = (const float*)d_in[9];
    const float* Wout  = (const float*)d_in[10];
    const float* bout  = (const float*)d_in[11];
    float* out = (float*)d_out;

    float *gi, *gic, *enc, *h0, *hvall, *hcall, *lp;
    __nv_bfloat16 *xh, *xl, *wh, *wl;
    cudaGetSymbolAddress((void**)&gi,    g_gi);
    cudaGetSymbolAddress((void**)&gic,   g_gic);
    cudaGetSymbolAddress((void**)&enc,   g_enc);
    cudaGetSymbolAddress((void**)&h0,    g_h0);
    cudaGetSymbolAddress((void**)&hvall, g_hvall);
    cudaGetSymbolAddress((void**)&hcall, g_hcall);
    cudaGetSymbolAddress((void**)&lp,    g_lpart);
    cudaGetSymbolAddress((void**)&xh,    g_xh);
    cudaGetSymbolAddress((void**)&xl,    g_xl);
    cudaGetSymbolAddress((void**)&wh,    g_wh);
    cudaGetSymbolAddress((void**)&wl,    g_wl);

    cudaFuncSetAttribute(scan_k, cudaFuncAttributeMaxDynamicSharedMemorySize, SMEM_BYTES);

    init_k<<<(NB*NWD + 255)/256, 256>>>(out);

    // gi_v via HMMA: bf16 split + 3-term GEMM on tensor pipe
    convx_k<<<((size_t)NT*NB*NF/4 + 255)/256, 256>>>(x, xh, xl);
    convw_k<<<((size_t)NG*NF/4 + 255)/256, 256>>>(Wih_v, wh, wl);
    mmagemm_k<<<dim3(NG/128, NT*NB/128), 256>>>(xh, xl, wh, wl, bih_v, gi);

    // encoder-v: chain = g_enc (== enc_out)
    scan_k<<<128, 256, SMEM_BYTES>>>(Whh_v, bhh_v, nullptr, gi, h0, enc, NT);

    // gi_c = enc_out @ Wih_c[:, :H]^T + bih_c -> g_gic
    gemm_k<<<dim3(NG/64, NT*NB/64), 128>>>(enc, Wih_c, bih_c, gic,
        NG, NH, NH, NH+NWD, NG, 0, 0);

    bar0_k<<<1, 32>>>();
    // encoder-c: chain = g_gi (gi_v dead)
    scan_k<<<128, 256, SMEM_BYTES>>>(Whh_c, bhh_c, nullptr, gic, h0, gi, NT);

    bar0_k<<<1, 32>>>();
    // decoder h_v chain
    scan_k<<<128, 256, SMEM_BYTES>>>(Whh_v, bhh_v, bih_v, nullptr,
        gi + (size_t)(NT-1)*BHSZ, hvall, NL-1);

    // batched decoder
    gemm_k<<<dim3(NG/64, 2048/64), 128>>>(hvall, Wih_c, bih_c, gic,
        NG, NH, NH, NH+NWD, NG, 0, 0);
    gemm_k<<<dim3(NG/64, 2048/64), 128>>>(hvall, Whh_c, bhh_c, gi,
        NG, NH, NH, NH, NG, 0, 0);
    dec_gates_k<<<((NL-1)*BHSZ + 255)/256, 256>>>(gic, gi, hvall, Wih_c, y, hcall);
    gemm_k<<<dim3((NWD + 63)/64, (NL-1)*NB/64), 128>>>(hcall, Wout, bout, out,
        NWD, NH, NH, NH, 0, 0, 1);

    loss1_k<<<NB, 256>>>(out, y, lp);
    loss2_k<<<1, 32>>>(lp, out);
}

// round 13
// speedup vs baseline: 1.7529x; 1.0783x over previous
#include <cuda_runtime.h>
#include <cuda_bf16.h>
#include <math.h>
#include <stdint.h>
#include <stddef.h>

#define NB 64
#define NT 80
#define NF 4096
#define NH 512
#define NG 1536
#define NWD 6000
#define NL 32
#define BHSZ (NB*NH)
#define OUTROW ((size_t)NL*NWD)

#define HP 516
#define WP 66
#define PBS (12*64)
#define SMEM_FLOATS (64*HP + 8*12*WP + 8*PBS)
#define SMEM_BYTES (SMEM_FLOATS*4)

__device__ float g_gi [NT*NB*NG];
__device__ float g_gic[NT*NB*NG];
__device__ float g_enc[NT*NB*NH];
__device__ float g_h0 [BHSZ];
__device__ float g_hvall[32*BHSZ];
__device__ float g_hcall[32*BHSZ];
__device__ float g_lpart[NB];
__device__ unsigned g_barrier;
__device__ __nv_bfloat16 g_xh[(size_t)NT*NB*NF];
__device__ __nv_bfloat16 g_xl[(size_t)NT*NB*NF];
__device__ __nv_bfloat16 g_wh[(size_t)NG*NF];
__device__ __nv_bfloat16 g_wl[(size_t)NG*NF];
__device__ __nv_bfloat16 g_hch[(size_t)32*BHSZ];
__device__ __nv_bfloat16 g_hcl[(size_t)32*BHSZ];
__device__ __nv_bfloat16 g_woh[(size_t)NWD*NH];
__device__ __nv_bfloat16 g_wol[(size_t)NWD*NH];

#define FMA2(d,a,b) asm("fma.rn.f32x2 %0, %1, %2, %0;" : "+l"(d) : "l"(a), "l"(b))
#define DUP(d,v)    asm("mov.b64 %0,{%1,%1};" : "=l"(d) : "f"(v))
#define UNPK(lo,hi,d) asm("mov.b64 {%0,%1}, %2;" : "=f"(lo), "=f"(hi) : "l"(d))
__device__ __forceinline__ float sigm(float x){ return 1.f/(1.f+expf(-x)); }

__device__ __forceinline__ void gridbar(unsigned& gen){
    __syncthreads();
    if (threadIdx.x == 0){
        gen += gridDim.x;
        asm volatile("red.release.gpu.global.add.u32 [%0], %1;" :: "l"(&g_barrier), "r"(1u) : "memory");
        unsigned v;
        do {
            __nanosleep(20);
            asm volatile("ld.acquire.gpu.global.u32 %0, [%1];" : "=r"(v) : "l"(&g_barrier) : "memory");
        } while (v < gen);
    }
    __syncthreads();
}

__device__ __forceinline__ uint32_t smem_u32(const void* p){
    uint32_t a;
    asm("{ .reg .u64 t; cvta.to.shared.u64 t, %1; cvt.u32.u64 %0, t; }" : "=r"(a) : "l"(p));
    return a;
}
#define LDSM4(r0,r1,r2,r3,addr) \
    asm volatile("ldmatrix.sync.aligned.m8n8.x4.shared.b16 {%0,%1,%2,%3}, [%4];" \
        : "=r"(r0),"=r"(r1),"=r"(r2),"=r"(r3) : "r"(addr))
#define MMA16816(d,a0,a1,a2,a3,b0,b1) \
    asm volatile("mma.sync.aligned.m16n8k16.row.col.f32.bf16.bf16.f32 " \
        "{%0,%1,%2,%3}, {%4,%5,%6,%7}, {%8,%9}, {%0,%1,%2,%3};" \
        : "+f"((d)[0]),"+f"((d)[1]),"+f"((d)[2]),"+f"((d)[3]) \
        : "r"(a0),"r"(a1),"r"(a2),"r"(a3), "r"(b0),"r"(b1))

// ======== HMMA 3-term split GEMM: C[Mreal,Nreal] = A @ B^T + bias ========
// phases: (ah,bh), (ah,bl), (al,bh). 128x128 tile, BK=32, double-buffered smem.
// cmode=1: C row m -> out[(m&63)*OUTROW + ((m>>6)+1)*NWD]
#define SPAD 40
__global__ __launch_bounds__(256, 2) void mmagemm_k(
    const __nv_bfloat16* __restrict__ ah, const __nv_bfloat16* __restrict__ al,
    const __nv_bfloat16* __restrict__ bh, const __nv_bfloat16* __restrict__ bl,
    const float* __restrict__ bias, float* __restrict__ C,
    int K, int Mreal, int Nreal, int ldc, int cmode)
{
    __shared__ __align__(16) __nv_bfloat16 As[2][128][SPAD];
    __shared__ __align__(16) __nv_bfloat16 Bs[2][128][SPAD];
    const int tid = threadIdx.x, wid = tid >> 5, lane = tid & 31;
    const int bn0 = blockIdx.x*128, bm0 = blockIdx.y*128;
    const int wm = (wid >> 2)*64, wn = (wid & 3)*32;

    float acc[4][4][4];
    #pragma unroll
    for (int i = 0; i < 4; i++)
        #pragma unroll
        for (int a = 0; a < 4; a++){ acc[i][a][0]=0.f; acc[i][a][1]=0.f; acc[i][a][2]=0.f; acc[i][a][3]=0.f; }

    const int srow = tid >> 2, sseg = (tid & 3)*8;
    const int a_r = lane & 15, a_c8 = (lane >> 4)*8;
    const int b_tile = lane >> 3, b_r = lane & 7;
    const int b_nrow_off = (b_tile >> 1)*8 + b_r;
    const int b_kcol_off = (b_tile & 1)*8;

    // clamped rows (M or N may not divide 128)
    int am0 = bm0 + srow;      if (am0 >= Mreal) am0 = Mreal - 1;
    int am1 = bm0 + srow + 64; if (am1 >= Mreal) am1 = Mreal - 1;
    int br0 = bn0 + srow;      if (br0 >= Nreal) br0 = Nreal - 1;
    int br1 = bn0 + srow + 64; if (br1 >= Nreal) br1 = Nreal - 1;
    const size_t ar0 = (size_t)am0*K, ar1 = (size_t)am1*K;
    const size_t brr0 = (size_t)br0*K, brr1 = (size_t)br1*K;

    const int chunks = K >> 5;
    const int total = 3*chunks;

    uint4 ra0, ra1, rb0, rb1;
    {   // chunk 0 (phase 0: ah, bh)
        ra0 = *(const uint4*)(ah + ar0 + sseg);
        ra1 = *(const uint4*)(ah + ar1 + sseg);
        rb0 = *(const uint4*)(bh + brr0 + sseg);
        rb1 = *(const uint4*)(bh + brr1 + sseg);
        *(uint4*)&As[0][srow   ][sseg] = ra0;
        *(uint4*)&As[0][srow+64][sseg] = ra1;
        *(uint4*)&Bs[0][srow   ][sseg] = rb0;
        *(uint4*)&Bs[0][srow+64][sseg] = rb1;
    }
    __syncthreads();

    for (int c = 0; c < total; c++){
        const int buf = c & 1;
        if (c + 1 < total){
            const int cn = c + 1;
            const int ph = cn / chunks;
            const int kin = (cn - ph*chunks) << 5;
            const __nv_bfloat16* sA = (ph < 2) ? ah : al;
            const __nv_bfloat16* sB = (ph == 1) ? bl : bh;
            ra0 = *(const uint4*)(sA + ar0 + kin + sseg);
            ra1 = *(const uint4*)(sA + ar1 + kin + sseg);
            rb0 = *(const uint4*)(sB + brr0 + kin + sseg);
            rb1 = *(const uint4*)(sB + brr1 + kin + sseg);
        }
        const uint32_t asmb = smem_u32(&As[buf][0][0]);
        const uint32_t bsmb = smem_u32(&Bs[buf][0][0]);
        #pragma unroll
        for (int kk = 0; kk < 2; kk++){
            uint32_t af[4][4];
            #pragma unroll
            for (int i = 0; i < 4; i++){
                uint32_t addr = asmb + (uint32_t)(((wm + i*16 + a_r)*SPAD + kk*16 + a_c8)*2);
                LDSM4(af[i][0], af[i][1], af[i][2], af[i][3], addr);
            }
            uint32_t bf[2][4];
            #pragma unroll
            for (int j = 0; j < 2; j++){
                uint32_t addr = bsmb + (uint32_t)(((wn + j*16 + b_nrow_off)*SPAD + kk*16 + b_kcol_off)*2);
                LDSM4(bf[j][0], bf[j][1], bf[j][2], bf[j][3], addr);
            }
            #pragma unroll
            for (int i = 0; i < 4; i++)
                #pragma unroll
                for (int a = 0; a < 4; a++)
                    MMA16816(acc[i][a], af[i][0], af[i][1], af[i][2], af[i][3],
                             bf[a>>1][(a&1)*2], bf[a>>1][(a&1)*2+1]);
        }
        if (c + 1 < total){
            const int nb = (c + 1) & 1;
            *(uint4*)&As[nb][srow   ][sseg] = ra0;
            *(uint4*)&As[nb][srow+64][sseg] = ra1;
            *(uint4*)&Bs[nb][srow   ][sseg] = rb0;
            *(uint4*)&Bs[nb][srow+64][sseg] = rb1;
            __syncthreads();
        }
    }

    const int gr = lane >> 2, gc = (lane & 3)*2;
    #pragma unroll
    for (int i = 0; i < 4; i++){
        #pragma unroll
        for (int a = 0; a < 4; a++){
            int m = bm0 + wm + i*16 + gr;
            int n = bn0 + wn + a*8 + gc;
            if (n >= Nreal) continue;
            float b0 = bias[n], b1 = bias[n+1];
            int m8 = m + 8;
            if (cmode == 1){
                if (m < Mreal){
                    float* c0 = C + (size_t)(m & 63)*OUTROW + (size_t)((m >> 6) + 1)*NWD + n;
                    *(float2*)c0 = make_float2(acc[i][a][0] + b0, acc[i][a][1] + b1);
                }
                if (m8 < Mreal){
                    float* c1 = C + (size_t)(m8 & 63)*OUTROW + (size_t)((m8 >> 6) + 1)*NWD + n;
                    *(float2*)c1 = make_float2(acc[i][a][2] + b0, acc[i][a][3] + b1);
                }
            } else {
                if (m < Mreal){
                    float* c0 = C + (size_t)m*ldc + n;
                    *(float2*)c0 = make_float2(acc[i][a][0] + b0, acc[i][a][1] + b1);
                }
                if (m8 < Mreal){
                    float* c1 = C + (size_t)m8*ldc + n;
                    *(float2*)c1 = make_float2(acc[i][a][2] + b0, acc[i][a][3] + b1);
                }
            }
        }
    }
}

// ============ bf16 split conversions ============
__global__ void convx_k(const float* __restrict__ x, __nv_bfloat16* __restrict__ xh,
                        __nv_bfloat16* __restrict__ xl){
    size_t i4 = ((size_t)blockIdx.x*blockDim.x + threadIdx.x)*4;
    if (i4 >= (size_t)NT*NB*NF) return;
    int m = (int)(i4 >> 12), f = (int)(i4 & 4095);
    int b = m & 63, t = m >> 6;
    float4 v = *(const float4*)(x + ((size_t)b*NT + t)*NF + f);
    float vv[4] = {v.x, v.y, v.z, v.w};
    __nv_bfloat16 h[4], l[4];
    #pragma unroll
    for (int e = 0; e < 4; e++){
        h[e] = __float2bfloat16(vv[e]);
        l[e] = __float2bfloat16(vv[e] - __bfloat162float(h[e]));
    }
    *(uint2*)(xh + i4) = *(uint2*)h;
    *(uint2*)(xl + i4) = *(uint2*)l;
}
__global__ void convg_k(const float* __restrict__ w, __nv_bfloat16* __restrict__ wh,
                        __nv_bfloat16* __restrict__ wl, size_t n4){
    size_t i = (size_t)blockIdx.x*blockDim.x + threadIdx.x;
    if (i >= n4) return;
    size_t i4 = i*4;
    float4 v = *(const float4*)(w + i4);
    float vv[4] = {v.x, v.y, v.z, v.w};
    __nv_bfloat16 h[4], l[4];
    #pragma unroll
    for (int e = 0; e < 4; e++){
        h[e] = __float2bfloat16(vv[e]);
        l[e] = __float2bfloat16(vv[e] - __bfloat162float(h[e]));
    }
    *(uint2*)(wh + i4) = *(uint2*)h;
    *(uint2*)(wl + i4) = *(uint2*)l;
}

// ====== proven 64x64 fp32 GEMM ======
__global__ __launch_bounds__(128) void gemm_k(
    const float* __restrict__ A, const float* __restrict__ B,
    const float* __restrict__ bias, float* __restrict__ C,
    int N, int K, int lda, int ldb, int ldc, int amode, int cmode)
{
    __shared__ __align__(16) float As[16][64];
    __shared__ __align__(16) float Bs[16][72];
    const int tid = threadIdx.x;
    const int bn0 = blockIdx.x*64;
    const int bm0 = blockIdx.y*64;
    const int lrow = tid >> 1, lk = (tid & 1)*8;
    const int am = bm0 + lrow;
    const float* arow;
    if (amode == 1){ int b_ = am & 63, t_ = am >> 6; arow = A + ((size_t)b_*NT + t_)*(size_t)lda; }
    else arow = A + (size_t)am*(size_t)lda;
    const float* brow = B + (size_t)(bn0 + lrow)*(size_t)ldb;
    const bool bval = (bn0 + lrow) < N;
    const int ty = tid >> 4, tx = tid & 15;

    unsigned long long acc[4][4];
    #pragma unroll
    for (int i = 0; i < 4; i++)
        #pragma unroll
        for (int j = 0; j < 4; j++) acc[i][j] = 0ull;

    for (int kk = 0; kk < K; kk += 16){
        float4 a0 = *(const float4*)(arow + kk + lk);
        float4 a1 = *(const float4*)(arow + kk + lk + 4);
        float4 b0 = make_float4(0.f,0.f,0.f,0.f), b1 = make_float4(0.f,0.f,0.f,0.f);
        if (bval){ b0 = *(const float4*)(brow + kk + lk); b1 = *(const float4*)(brow + kk + lk + 4); }
        As[lk+0][lrow]=a0.x; As[lk+1][lrow]=a0.y; As[lk+2][lrow]=a0.z; As[lk+3][lrow]=a0.w;
        As[lk+4][lrow]=a1.x; As[lk+5][lrow]=a1.y; As[lk+6][lrow]=a1.z; As[lk+7][lrow]=a1.w;
        Bs[lk+0][lrow]=b0.x; Bs[lk+1][lrow]=b0.y; Bs[lk+2][lrow]=b0.z; Bs[lk+3][lrow]=b0.w;
        Bs[lk+4][lrow]=b1.x; Bs[lk+5][lrow]=b1.y; Bs[lk+6][lrow]=b1.z; Bs[lk+7][lrow]=b1.w;
        __syncthreads();
        #pragma unroll
        for (int k = 0; k < 16; k++){
            const float* ap = &As[k][ty*8];
            unsigned long long av[4];
            av[0] = *(const unsigned long long*)(ap+0);
            av[1] = *(const unsigned long long*)(ap+2);
            av[2] = *(const unsigned long long*)(ap+4);
            av[3] = *(const unsigned long long*)(ap+6);
            float4 bv = *(const float4*)&Bs[k][tx*4];
            unsigned long long bd0,bd1,bd2,bd3;
            DUP(bd0, bv.x); DUP(bd1, bv.y); DUP(bd2, bv.z); DUP(bd3, bv.w);
            #pragma unroll
            for (int i = 0; i < 4; i++){
                FMA2(acc[i][0], av[i], bd0);
                FMA2(acc[i][1], av[i], bd1);
                FMA2(acc[i][2], av[i], bd2);
                FMA2(acc[i][3], av[i], bd3);
            }
        }
        __syncthreads();
    }
    #pragma unroll
    for (int i = 0; i < 4; i++){
        int m = bm0 + ty*8 + 2*i;
        float *r0, *r1;
        if (cmode == 1){
            r0 = C + (size_t)(m & 63)*OUTROW + (size_t)((m >> 6) + 1)*NWD;
            r1 = C + (size_t)((m+1) & 63)*OUTROW + (size_t)(((m+1) >> 6) + 1)*NWD;
        } else {
            r0 = C + (size_t)m*ldc;
            r1 = r0 + ldc;
        }
        #pragma unroll
        for (int j = 0; j < 4; j++){
            int n = bn0 + tx*4 + j;
            if (n < N){
                float lo, hi; UNPK(lo, hi, acc[i][j]);
                float bb = bias[n];
                r0[n] = lo + bb;
                r1[n] = hi + bb;
            }
        }
    }
}

// ================= persistent scan =================
__device__ __forceinline__ void stage_h(const float* __restrict__ src, float* __restrict__ hs){
    int t = threadIdx.x;
    #pragma unroll
    for (int i = 0; i < 32; i++){
        int lin = (i*256 + t)*4;
        int b = lin >> 9, k = lin & 511;
        *(float4*)(hs + b*HP + k) = *(const float4*)(src + lin);
    }
}
__device__ __forceinline__ void stage_w(const float* __restrict__ W, int ld, int base,
                                        int kbase, float* __restrict__ dst){
    int lane = threadIdx.x & 31;
    #pragma unroll
    for (int r = 0; r < 12; r++){
        int row = (r>>2)*NH + base + (r&3);
        float2 v = *(const float2*)(W + (size_t)row*ld + kbase + 2*lane);
        *(float2*)(dst + r*WP + 2*lane) = v;
    }
    __syncwarp();
}
__device__ __forceinline__ void micro_mm(const float* __restrict__ hs,
                                         const float* __restrict__ wr,
                                         float* __restrict__ pb, int kbase){
    int lane = threadIdx.x & 31;
    int cjp = lane & 3, mg = lane >> 2;
    unsigned long long acc[8][3];
    #pragma unroll
    for (int i = 0; i < 8; i++){ acc[i][0]=0ull; acc[i][1]=0ull; acc[i][2]=0ull; }
    const float* hp = hs + mg*HP + kbase;
    const float* w0 = wr + cjp*WP;
    #pragma unroll 4
    for (int k = 0; k < 64; k += 2){
        unsigned long long wv0 = *(const unsigned long long*)(w0 + k);
        unsigned long long wv1 = *(const unsigned long long*)(w0 + 4*WP + k);
        unsigned long long wv2 = *(const unsigned long long*)(w0 + 8*WP + k);
        #pragma unroll
        for (int i = 0; i < 8; i++){
            unsigned long long a = *(const unsigned long long*)(hp + i*8*HP + k);
            FMA2(acc[i][0], a, wv0);
            FMA2(acc[i][1], a, wv1);
            FMA2(acc[i][2], a, wv2);
        }
    }
    #pragma unroll
    for (int i = 0; i < 8; i++){
        int m = mg + 8*i;
        #pragma unroll
        for (int g = 0; g < 3; g++){
            float lo, hi; UNPK(lo, hi, acc[i][g]);
            pb[(g*4 + cjp)*64 + m] = lo + hi;
        }
    }
}
__device__ __forceinline__ float psum(const float* __restrict__ pbuf, int r, int b){
    float s = 0.f;
    #pragma unroll
    for (int w = 0; w < 8; w++) s += pbuf[(w*12 + r)*64 + b];
    return s;
}

__global__ __launch_bounds__(256,1) void scan_k(
    const float* __restrict__ Whh, const float* __restrict__ bhh,
    const float* __restrict__ bih, const float* __restrict__ gi_all,
    const float* __restrict__ h0, float* __restrict__ chain, int steps)
{
    extern __shared__ float sm[];
    float* hs = sm;
    float* wst = sm + 64*HP;
    float* pbuf = wst + 8*12*WP;
    const int tid = threadIdx.x, w = tid >> 5;
    const int c0 = blockIdx.x*4, kbase = w*64;
    float* wstw = wst + w*12*WP;
    float* pbw = pbuf + w*PBS;
    const int b = tid & 63, cj = tid >> 6;
    const int c = c0 + cj;
    unsigned gen = 0;

    stage_w(Whh, NH, c0, kbase, wstw);
    const float bhr = bhh[c], bhz = bhh[NH+c], bhn = bhh[2*NH+c];

    for (int step = 0; step < steps; step++){
        const float* hin = step ? (chain + (size_t)(step-1)*BHSZ) : h0;
        float* hout = chain + (size_t)step*BHSZ;
        const float* gp = gi_all ? (gi_all + ((size_t)step*NB + b)*NG) : bih;
        float gir = gp[c], giz = gp[NH+c], gin = gp[2*NH+c];
        stage_h(hin, hs);
        __syncthreads();
        micro_mm(hs, wstw, pbw, kbase);
        __syncthreads();
        {
            float ghr = bhr + psum(pbuf, cj, b);
            float ghz = bhz + psum(pbuf, 4+cj, b);
            float ghn = bhn + psum(pbuf, 8+cj, b);
            float r  = sigm(gir + ghr);
            float z  = sigm(giz + ghz);
            float nn = tanhf(gin + r*ghn);
            hout[b*NH + c] = (1.f - z)*nn + z*hs[b*HP + c];
        }
        gridbar(gen);
    }
}

// ================= batched decoder gates =================
__global__ void dec_gates_k(const float* __restrict__ gi_all, const float* __restrict__ gh_all,
                            const float* __restrict__ hv_all, const float* __restrict__ Wc,
                            const int* __restrict__ y, float* __restrict__ hc_all)
{
    int idx = blockIdx.x*blockDim.x + threadIdx.x;
    if (idx >= (NL-1)*BHSZ) return;
    int s = idx / BHSZ, r = idx % BHSZ;
    int b = r >> 9, c = r & 511;
    size_t m = (size_t)s*NB + b;
    const float* gi = gi_all + m*NG;
    const float* gh = gh_all + m*NG;
    int yb = y[s*NB + b];
    float gir = gi[c]      + Wc[(size_t)c*(NH+NWD)        + NH + yb];
    float giz = gi[NH+c]   + Wc[(size_t)(NH+c)*(NH+NWD)   + NH + yb];
    float gin = gi[2*NH+c] + Wc[(size_t)(2*NH+c)*(NH+NWD) + NH + yb];
    float rr = sigm(gir + gh[c]);
    float zz = sigm(giz + gh[NH+c]);
    float nn = tanhf(gin + rr*gh[2*NH+c]);
    hc_all[(size_t)s*BHSZ + r] = (1.f - zz)*nn + zz*hv_all[(size_t)s*BHSZ + r];
}

// ================= misc =================
__global__ void init_k(float* __restrict__ out){
    int idx = blockIdx.x*blockDim.x + threadIdx.x;
    if (idx < NB*NWD){
        int b = idx / NWD, n = idx % NWD;
        out[(size_t)b*OUTROW + n] = (b == 0 && n == 1) ? 1.f : 0.f;
    }
    if (idx < BHSZ) g_h0[idx] = 0.f;
    if (idx == 0) g_barrier = 0u;
}
__global__ void bar0_k(){ if (threadIdx.x == 0) g_barrier = 0u; }
__global__ void loss1_k(const float* __restrict__ out, const int* __restrict__ y,
                        float* __restrict__ part){
    int b = blockIdx.x;
    const float* row = out + (size_t)b*OUTROW + (size_t)(NL-1)*NWD;
    __shared__ float red[256];
    float m = -1e30f;
    for (int i = threadIdx.x; i < NWD; i += 256) m = fmaxf(m, row[i]);
    red[threadIdx.x] = m; __syncthreads();
    for (int s = 128; s > 0; s >>= 1){ if (threadIdx.x < s) red[threadIdx.x] = fmaxf(red[threadIdx.x], red[threadIdx.x+s]); __syncthreads(); }
    m = red[0]; __syncthreads();
    float sum = 0.f;
    for (int i = threadIdx.x; i < NWD; i += 256) sum += expf(row[i] - m);
    red[threadIdx.x] = sum; __syncthreads();
    for (int s = 128; s > 0; s >>= 1){ if (threadIdx.x < s) red[threadIdx.x] += red[threadIdx.x+s]; __syncthreads(); }
    if (threadIdx.x == 0){
        int t = y[(NL-1)*NB + b];
        part[b] = -(row[t] - m - logf(red[0]));
    }
}
__global__ void loss2_k(const float* __restrict__ part, float* __restrict__ out){
    if (threadIdx.x == 0){
        float s = 0.f;
        for (int b = 0; b < NB; b++) s += part[b];
        out[(size_t)NB*NL*NWD] = s/(float)NB;
    }
}

extern "C" void kernel_launch(void* const* d_in, const int* in_sizes, int n_in,
                              void* d_out, int out_size){
    const float* x     = (const float*)d_in[0];
    const int*   y     = (const int*)  d_in[1];
    const float* Wih_v = (const float*)d_in[2];
    const float* Whh_v = (const float*)d_in[3];
    const float* bih_v = (const float*)d_in[4];
    const float* bhh_v = (const float*)d_in[5];
    const float* Wih_c = (const float*)d_in[6];
    const float* Whh_c = (const float*)d_in[7];
    const float* bih_c = (const float*)d_in[8];
    const float* bhh_c = (const float*)d_in[9];
    const float* Wout  = (const float*)d_in[10];
    const float* bout  = (const float*)d_in[11];
    float* out = (float*)d_out;

    float *gi, *gic, *enc, *h0, *hvall, *hcall, *lp;
    __nv_bfloat16 *xh, *xl, *wh, *wl, *hch, *hcl, *woh, *wol;
    cudaGetSymbolAddress((void**)&gi,    g_gi);
    cudaGetSymbolAddress((void**)&gic,   g_gic);
    cudaGetSymbolAddress((void**)&enc,   g_enc);
    cudaGetSymbolAddress((void**)&h0,    g_h0);
    cudaGetSymbolAddress((void**)&hvall, g_hvall);
    cudaGetSymbolAddress((void**)&hcall, g_hcall);
    cudaGetSymbolAddress((void**)&lp,    g_lpart);
    cudaGetSymbolAddress((void**)&xh,    g_xh);
    cudaGetSymbolAddress((void**)&xl,    g_xl);
    cudaGetSymbolAddress((void**)&wh,    g_wh);
    cudaGetSymbolAddress((void**)&wl,    g_wl);
    cudaGetSymbolAddress((void**)&hch,   g_hch);
    cudaGetSymbolAddress((void**)&hcl,   g_hcl);
    cudaGetSymbolAddress((void**)&woh,   g_woh);
    cudaGetSymbolAddress((void**)&wol,   g_wol);

    cudaFuncSetAttribute(scan_k, cudaFuncAttributeMaxDynamicSharedMemorySize, SMEM_BYTES);

    init_k<<<(NB*NWD + 255)/256, 256>>>(out);

    // gi_v via HMMA (double-buffered), M=5120 divides 128
    convx_k<<<((size_t)NT*NB*NF/4 + 255)/256, 256>>>(x, xh, xl);
    convg_k<<<((size_t)NG*NF/4 + 255)/256, 256>>>(Wih_v, wh, wl, (size_t)NG*NF/4);
    convg_k<<<((size_t)NWD*NH/4 + 255)/256, 256>>>(Wout, woh, wol, (size_t)NWD*NH/4);
    mmagemm_k<<<dim3(NG/128, NT*NB/128), 256>>>(xh, xl, wh, wl, bih_v, gi,
        NF, NT*NB, NG, NG, 0);

    // encoder-v
    scan_k<<<128, 256, SMEM_BYTES>>>(Whh_v, bhh_v, nullptr, gi, h0, enc, NT);

    // gi_c
    gemm_k<<<dim3(NG/64, NT*NB/64), 128>>>(enc, Wih_c, bih_c, gic,
        NG, NH, NH, NH+NWD, NG, 0, 0);

    bar0_k<<<1, 32>>>();
    scan_k<<<128, 256, SMEM_BYTES>>>(Whh_c, bhh_c, nullptr, gic, h0, gi, NT);

    bar0_k<<<1, 32>>>();
    scan_k<<<128, 256, SMEM_BYTES>>>(Whh_v, bhh_v, bih_v, nullptr,
        gi + (size_t)(NT-1)*BHSZ, hvall, NL-1);

    // batched decoder
    gemm_k<<<dim3(NG/64, 2048/64), 128>>>(hvall, Wih_c, bih_c, gic,
        NG, NH, NH, NH+NWD, NG, 0, 0);
    gemm_k<<<dim3(NG/64, 2048/64), 128>>>(hvall, Whh_c, bhh_c, gi,
        NG, NH, NH, NH, NG, 0, 0);
    dec_gates_k<<<((NL-1)*BHSZ + 255)/256, 256>>>(gic, gi, hvall, Wih_c, y, hcall);
    // logits on HMMA — grid.y CEILED (1984 = 15.5*128; was the R12 bug), Mreal guards stores
    convg_k<<<((size_t)(NL-1)*BHSZ/4 + 255)/256, 256>>>(hcall, hch, hcl, (size_t)(NL-1)*BHSZ/4);
    mmagemm_k<<<dim3((NWD + 127)/128, ((NL-1)*NB + 127)/128), 256>>>(hch, hcl, woh, wol, bout, out,
        NH, (NL-1)*NB, NWD, 0, 1);

    loss1_k<<<NB, 256>>>(out, y, lp);
    loss2_k<<<1, 32>>>(lp, out);
}

// round 17
// speedup vs baseline: 1.9460x; 1.1101x over previous
#include <cuda_runtime.h>
#include <cuda_bf16.h>
#include <math.h>
#include <stdint.h>
#include <stddef.h>

#define NB 64
#define NT 80
#define NF 4096
#define NH 512
#define NG 1536
#define NWD 6000
#define NL 32
#define BHSZ (NB*NH)
#define OUTROW ((size_t)NL*NWD)

#define HP 516
#define WP 66
#define PBS (12*64)
#define SMEM_FLOATS (64*HP + 8*12*WP + 8*PBS)
#define SMEM_BYTES (SMEM_FLOATS*4)

__device__ float g_gi [NT*NB*NG];
__device__ float g_gic[NT*NB*NG];
__device__ float g_enc[NT*NB*NH];
__device__ float g_h0 [BHSZ];
__device__ float g_hvall[32*BHSZ];
__device__ float g_hcall[32*BHSZ];
__device__ float g_lpart[NB];
__device__ unsigned g_barrier;
__device__ __nv_bfloat16 g_xh[(size_t)NT*NB*NF];
__device__ __nv_bfloat16 g_xl[(size_t)NT*NB*NF];
__device__ __nv_bfloat16 g_wh[(size_t)NG*NF];
__device__ __nv_bfloat16 g_wl[(size_t)NG*NF];
__device__ __nv_bfloat16 g_hch[(size_t)32*BHSZ];   // hv-split, then hc-split (disjoint lifetimes)
__device__ __nv_bfloat16 g_hcl[(size_t)32*BHSZ];
__device__ __nv_bfloat16 g_woh[(size_t)NWD*NH];
__device__ __nv_bfloat16 g_wol[(size_t)NWD*NH];
__device__ __nv_bfloat16 g_ench[(size_t)NT*NB*NH];
__device__ __nv_bfloat16 g_encl[(size_t)NT*NB*NH];
__device__ __nv_bfloat16 g_wch[(size_t)NG*NH];     // Wih_c[:, :H] packed
__device__ __nv_bfloat16 g_wcl[(size_t)NG*NH];
__device__ __nv_bfloat16 g_whhch[(size_t)NG*NH];   // Whh_c
__device__ __nv_bfloat16 g_whhcl[(size_t)NG*NH];

#define FMA2(d,a,b) asm("fma.rn.f32x2 %0, %1, %2, %0;" : "+l"(d) : "l"(a), "l"(b))
#define DUP(d,v)    asm("mov.b64 %0,{%1,%1};" : "=l"(d) : "f"(v))
#define UNPK(lo,hi,d) asm("mov.b64 {%0,%1}, %2;" : "=f"(lo), "=f"(hi) : "l"(d))
__device__ __forceinline__ float sigm(float x){ return 1.f/(1.f+expf(-x)); }

__device__ __forceinline__ void gridbar(unsigned& gen){
    __syncthreads();
    if (threadIdx.x == 0){
        gen += gridDim.x;
        asm volatile("red.release.gpu.global.add.u32 [%0], %1;" :: "l"(&g_barrier), "r"(1u) : "memory");
        unsigned v;
        do {
            __nanosleep(20);
            asm volatile("ld.acquire.gpu.global.u32 %0, [%1];" : "=r"(v) : "l"(&g_barrier) : "memory");
        } while (v < gen);
    }
    __syncthreads();
}

__device__ __forceinline__ uint32_t smem_u32(const void* p){
    uint32_t a;
    asm("{ .reg .u64 t; cvta.to.shared.u64 t, %1; cvt.u32.u64 %0, t; }" : "=r"(a) : "l"(p));
    return a;
}
#define LDSM4(r0,r1,r2,r3,addr) \
    asm volatile("ldmatrix.sync.aligned.m8n8.x4.shared.b16 {%0,%1,%2,%3}, [%4];" \
        : "=r"(r0),"=r"(r1),"=r"(r2),"=r"(r3) : "r"(addr))
#define MMA16816(d,a0,a1,a2,a3,b0,b1) \
    asm volatile("mma.sync.aligned.m16n8k16.row.col.f32.bf16.bf16.f32 " \
        "{%0,%1,%2,%3}, {%4,%5,%6,%7}, {%8,%9}, {%0,%1,%2,%3};" \
        : "+f"((d)[0]),"+f"((d)[1]),"+f"((d)[2]),"+f"((d)[3]) \
        : "r"(a0),"r"(a1),"r"(a2),"r"(a3), "r"(b0),"r"(b1))

// ======== HMMA 3-term split GEMM: C[Mreal,Nreal] = A @ B^T + bias ========
#define SPAD 40
__global__ __launch_bounds__(256, 2) void mmagemm_k(
    const __nv_bfloat16* __restrict__ ah, const __nv_bfloat16* __restrict__ al,
    const __nv_bfloat16* __restrict__ bh, const __nv_bfloat16* __restrict__ bl,
    const float* __restrict__ bias, float* __restrict__ C,
    int K, int Mreal, int Nreal, int ldc, int cmode)
{
    __shared__ __align__(16) __nv_bfloat16 As[2][128][SPAD];
    __shared__ __align__(16) __nv_bfloat16 Bs[2][128][SPAD];
    const int tid = threadIdx.x, wid = tid >> 5, lane = tid & 31;
    const int bn0 = blockIdx.x*128, bm0 = blockIdx.y*128;
    const int wm = (wid >> 2)*64, wn = (wid & 3)*32;

    float acc[4][4][4];
    #pragma unroll
    for (int i = 0; i < 4; i++)
        #pragma unroll
        for (int a = 0; a < 4; a++){ acc[i][a][0]=0.f; acc[i][a][1]=0.f; acc[i][a][2]=0.f; acc[i][a][3]=0.f; }

    const int srow = tid >> 2, sseg = (tid & 3)*8;
    const int a_r = lane & 15, a_c8 = (lane >> 4)*8;
    const int b_tile = lane >> 3, b_r = lane & 7;
    const int b_nrow_off = (b_tile >> 1)*8 + b_r;
    const int b_kcol_off = (b_tile & 1)*8;

    int am0 = bm0 + srow;      if (am0 >= Mreal) am0 = Mreal - 1;
    int am1 = bm0 + srow + 64; if (am1 >= Mreal) am1 = Mreal - 1;
    int br0 = bn0 + srow;      if (br0 >= Nreal) br0 = Nreal - 1;
    int br1 = bn0 + srow + 64; if (br1 >= Nreal) br1 = Nreal - 1;
    const size_t ar0 = (size_t)am0*K, ar1 = (size_t)am1*K;
    const size_t brr0 = (size_t)br0*K, brr1 = (size_t)br1*K;

    const int chunks = K >> 5;
    const int total = 3*chunks;

    uint4 ra0, ra1, rb0, rb1;
    {
        ra0 = *(const uint4*)(ah + ar0 + sseg);
        ra1 = *(const uint4*)(ah + ar1 + sseg);
        rb0 = *(const uint4*)(bh + brr0 + sseg);
        rb1 = *(const uint4*)(bh + brr1 + sseg);
        *(uint4*)&As[0][srow   ][sseg] = ra0;
        *(uint4*)&As[0][srow+64][sseg] = ra1;
        *(uint4*)&Bs[0][srow   ][sseg] = rb0;
        *(uint4*)&Bs[0][srow+64][sseg] = rb1;
    }
    __syncthreads();

    for (int c = 0; c < total; c++){
        const int buf = c & 1;
        if (c + 1 < total){
            const int cn = c + 1;
            const int ph = cn / chunks;
            const int kin = (cn - ph*chunks) << 5;
            const __nv_bfloat16* sA = (ph < 2) ? ah : al;
            const __nv_bfloat16* sB = (ph == 1) ? bl : bh;
            ra0 = *(const uint4*)(sA + ar0 + kin + sseg);
            ra1 = *(const uint4*)(sA + ar1 + kin + sseg);
            rb0 = *(const uint4*)(sB + brr0 + kin + sseg);
            rb1 = *(const uint4*)(sB + brr1 + kin + sseg);
        }
        const uint32_t asmb = smem_u32(&As[buf][0][0]);
        const uint32_t bsmb = smem_u32(&Bs[buf][0][0]);
        #pragma unroll
        for (int kk = 0; kk < 2; kk++){
            uint32_t af[4][4];
            #pragma unroll
            for (int i = 0; i < 4; i++){
                uint32_t addr = asmb + (uint32_t)(((wm + i*16 + a_r)*SPAD + kk*16 + a_c8)*2);
                LDSM4(af[i][0], af[i][1], af[i][2], af[i][3], addr);
            }
            uint32_t bf[2][4];
            #pragma unroll
            for (int j = 0; j < 2; j++){
                uint32_t addr = bsmb + (uint32_t)(((wn + j*16 + b_nrow_off)*SPAD + kk*16 + b_kcol_off)*2);
                LDSM4(bf[j][0], bf[j][1], bf[j][2], bf[j][3], addr);
            }
            #pragma unroll
            for (int i = 0; i < 4; i++)
                #pragma unroll
                for (int a = 0; a < 4; a++)
                    MMA16816(acc[i][a], af[i][0], af[i][1], af[i][2], af[i][3],
                             bf[a>>1][(a&1)*2], bf[a>>1][(a&1)*2+1]);
        }
        if (c + 1 < total){
            const int nb = (c + 1) & 1;
            *(uint4*)&As[nb][srow   ][sseg] = ra0;
            *(uint4*)&As[nb][srow+64][sseg] = ra1;
            *(uint4*)&Bs[nb][srow   ][sseg] = rb0;
            *(uint4*)&Bs[nb][srow+64][sseg] = rb1;
            __syncthreads();
        }
    }

    const int gr = lane >> 2, gc = (lane & 3)*2;
    #pragma unroll
    for (int i = 0; i < 4; i++){
        #pragma unroll
        for (int a = 0; a < 4; a++){
            int m = bm0 + wm + i*16 + gr;
            int n = bn0 + wn + a*8 + gc;
            if (n >= Nreal) continue;
            float b0 = bias[n], b1 = bias[n+1];
            int m8 = m + 8;
            if (cmode == 1){
                if (m < Mreal){
                    float* c0 = C + (size_t)(m & 63)*OUTROW + (size_t)((m >> 6) + 1)*NWD + n;
                    *(float2*)c0 = make_float2(acc[i][a][0] + b0, acc[i][a][1] + b1);
                }
                if (m8 < Mreal){
                    float* c1 = C + (size_t)(m8 & 63)*OUTROW + (size_t)((m8 >> 6) + 1)*NWD + n;
                    *(float2*)c1 = make_float2(acc[i][a][2] + b0, acc[i][a][3] + b1);
                }
            } else {
                if (m < Mreal){
                    float* c0 = C + (size_t)m*ldc + n;
                    *(float2*)c0 = make_float2(acc[i][a][0] + b0, acc[i][a][1] + b1);
                }
                if (m8 < Mreal){
                    float* c1 = C + (size_t)m8*ldc + n;
                    *(float2*)c1 = make_float2(acc[i][a][2] + b0, acc[i][a][3] + b1);
                }
            }
        }
    }
}

// ============ bf16 split conversions ============
__global__ void convx_k(const float* __restrict__ x, __nv_bfloat16* __restrict__ xh,
                        __nv_bfloat16* __restrict__ xl){
    size_t i4 = ((size_t)blockIdx.x*blockDim.x + threadIdx.x)*4;
    if (i4 >= (size_t)NT*NB*NF) return;
    int m = (int)(i4 >> 12), f = (int)(i4 & 4095);
    int b = m & 63, t = m >> 6;
    float4 v = *(const float4*)(x + ((size_t)b*NT + t)*NF + f);
    float vv[4] = {v.x, v.y, v.z, v.w};
    __nv_bfloat16 h[4], l[4];
    #pragma unroll
    for (int e = 0; e < 4; e++){
        h[e] = __float2bfloat16(vv[e]);
        l[e] = __float2bfloat16(vv[e] - __bfloat162float(h[e]));
    }
    *(uint2*)(xh + i4) = *(uint2*)h;
    *(uint2*)(xl + i4) = *(uint2*)l;
}
__global__ void convg_k(const float* __restrict__ w, __nv_bfloat16* __restrict__ wh,
                        __nv_bfloat16* __restrict__ wl, size_t n4){
    size_t i = (size_t)blockIdx.x*blockDim.x + threadIdx.x;
    if (i >= n4) return;
    size_t i4 = i*4;
    float4 v = *(const float4*)(w + i4);
    float vv[4] = {v.x, v.y, v.z, v.w};
    __nv_bfloat16 h[4], l[4];
    #pragma unroll
    for (int e = 0; e < 4; e++){
        h[e] = __float2bfloat16(vv[e]);
        l[e] = __float2bfloat16(vv[e] - __bfloat162float(h[e]));
    }
    *(uint2*)(wh + i4) = *(uint2*)h;
    *(uint2*)(wl + i4) = *(uint2*)l;
}
// strided rows: pack W[r*ld + c], c<cols into dst[r*cols + c]
__global__ void convs_k(const float* __restrict__ w, int ld, int rows, int cols,
                        __nv_bfloat16* __restrict__ wh, __nv_bfloat16* __restrict__ wl){
    size_t i4 = ((size_t)blockIdx.x*blockDim.x + threadIdx.x)*4;
    if (i4 >= (size_t)rows*cols) return;
    int r = (int)(i4 / cols), c = (int)(i4 % cols);
    float4 v = *(const float4*)(w + (size_t)r*ld + c);
    float vv[4] = {v.x, v.y, v.z, v.w};
    __nv_bfloat16 h[4], l[4];
    #pragma unroll
    for (int e = 0; e < 4; e++){
        h[e] = __float2bfloat16(vv[e]);
        l[e] = __float2bfloat16(vv[e] - __bfloat162float(h[e]));
    }
    *(uint2*)(wh + i4) = *(uint2*)h;
    *(uint2*)(wl + i4) = *(uint2*)l;
}

// ================= persistent scan =================
__device__ __forceinline__ void stage_h(const float* __restrict__ src, float* __restrict__ hs){
    int t = threadIdx.x;
    #pragma unroll
    for (int i = 0; i < 32; i++){
        int lin = (i*256 + t)*4;
        int b = lin >> 9, k = lin & 511;
        *(float4*)(hs + b*HP + k) = *(const float4*)(src + lin);
    }
}
__device__ __forceinline__ void stage_w(const float* __restrict__ W, int ld, int base,
                                        int kbase, float* __restrict__ dst){
    int lane = threadIdx.x & 31;
    #pragma unroll
    for (int r = 0; r < 12; r++){
        int row = (r>>2)*NH + base + (r&3);
        float2 v = *(const float2*)(W + (size_t)row*ld + kbase + 2*lane);
        *(float2*)(dst + r*WP + 2*lane) = v;
    }
    __syncwarp();
}
__device__ __forceinline__ void micro_mm(const float* __restrict__ hs,
                                         const float* __restrict__ wr,
                                         float* __restrict__ pb, int kbase){
    int lane = threadIdx.x & 31;
    int cjp = lane & 3, mg = lane >> 2;
    unsigned long long acc[8][3];
    #pragma unroll
    for (int i = 0; i < 8; i++){ acc[i][0]=0ull; acc[i][1]=0ull; acc[i][2]=0ull; }
    const float* hp = hs + mg*HP + kbase;
    const float* w0 = wr + cjp*WP;
    #pragma unroll 4
    for (int k = 0; k < 64; k += 2){
        unsigned long long wv0 = *(const unsigned long long*)(w0 + k);
        unsigned long long wv1 = *(const unsigned long long*)(w0 + 4*WP + k);
        unsigned long long wv2 = *(const unsigned long long*)(w0 + 8*WP + k);
        #pragma unroll
        for (int i = 0; i < 8; i++){
            unsigned long long a = *(const unsigned long long*)(hp + i*8*HP + k);
            FMA2(acc[i][0], a, wv0);
            FMA2(acc[i][1], a, wv1);
            FMA2(acc[i][2], a, wv2);
        }
    }
    #pragma unroll
    for (int i = 0; i < 8; i++){
        int m = mg + 8*i;
        #pragma unroll
        for (int g = 0; g < 3; g++){
            float lo, hi; UNPK(lo, hi, acc[i][g]);
            pb[(g*4 + cjp)*64 + m] = lo + hi;
        }
    }
}
__device__ __forceinline__ float psum(const float* __restrict__ pbuf, int r, int b){
    float s = 0.f;
    #pragma unroll
    for (int w = 0; w < 8; w++) s += pbuf[(w*12 + r)*64 + b];
    return s;
}

__global__ __launch_bounds__(256,1) void scan_k(
    const float* __restrict__ Whh, const float* __restrict__ bhh,
    const float* __restrict__ bih, const float* __restrict__ gi_all,
    const float* __restrict__ h0, float* __restrict__ chain, int steps)
{
    extern __shared__ float sm[];
    float* hs = sm;
    float* wst = sm + 64*HP;
    float* pbuf = wst + 8*12*WP;
    const int tid = threadIdx.x, w = tid >> 5;
    const int c0 = blockIdx.x*4, kbase = w*64;
    float* wstw = wst + w*12*WP;
    float* pbw = pbuf + w*PBS;
    const int b = tid & 63, cj = tid >> 6;
    const int c = c0 + cj;
    unsigned gen = 0;

    stage_w(Whh, NH, c0, kbase, wstw);
    const float bhr = bhh[c], bhz = bhh[NH+c], bhn = bhh[2*NH+c];

    for (int step = 0; step < steps; step++){
        const float* hin = step ? (chain + (size_t)(step-1)*BHSZ) : h0;
        float* hout = chain + (size_t)step*BHSZ;
        const float* gp = gi_all ? (gi_all + ((size_t)step*NB + b)*NG) : bih;
        float gir = gp[c], giz = gp[NH+c], gin = gp[2*NH+c];
        stage_h(hin, hs);
        __syncthreads();
        micro_mm(hs, wstw, pbw, kbase);
        __syncthreads();
        {
            float ghr = bhr + psum(pbuf, cj, b);
            float ghz = bhz + psum(pbuf, 4+cj, b);
            float ghn = bhn + psum(pbuf, 8+cj, b);
            float r  = sigm(gir + ghr);
            float z  = sigm(giz + ghz);
            float nn = tanhf(gin + r*ghn);
            hout[b*NH + c] = (1.f - z)*nn + z*hs[b*HP + c];
        }
        gridbar(gen);
    }
}

// ================= batched decoder gates =================
__global__ void dec_gates_k(const float* __restrict__ gi_all, const float* __restrict__ gh_all,
                            const float* __restrict__ hv_all, const float* __restrict__ Wc,
                            const int* __restrict__ y, float* __restrict__ hc_all)
{
    int idx = blockIdx.x*blockDim.x + threadIdx.x;
    if (idx >= (NL-1)*BHSZ) return;
    int s = idx / BHSZ, r = idx % BHSZ;
    int b = r >> 9, c = r & 511;
    size_t m = (size_t)s*NB + b;
    const float* gi = gi_all + m*NG;
    const float* gh = gh_all + m*NG;
    int yb = y[s*NB + b];
    float gir = gi[c]      + Wc[(size_t)c*(NH+NWD)        + NH + yb];
    float giz = gi[NH+c]   + Wc[(size_t)(NH+c)*(NH+NWD)   + NH + yb];
    float gin = gi[2*NH+c] + Wc[(size_t)(2*NH+c)*(NH+NWD) + NH + yb];
    float rr = sigm(gir + gh[c]);
    float zz = sigm(giz + gh[NH+c]);
    float nn = tanhf(gin + rr*gh[2*NH+c]);
    hc_all[(size_t)s*BHSZ + r] = (1.f - zz)*nn + zz*hv_all[(size_t)s*BHSZ + r];
}

// ================= misc =================
__global__ void init_k(float* __restrict__ out){
    int idx = blockIdx.x*blockDim.x + threadIdx.x;
    if (idx < NB*NWD){
        int b = idx / NWD, n = idx % NWD;
        out[(size_t)b*OUTROW + n] = (b == 0 && n == 1) ? 1.f : 0.f;
    }
    if (idx < BHSZ) g_h0[idx] = 0.f;
    if (idx == 0) g_barrier = 0u;
}
__global__ void bar0_k(){ if (threadIdx.x == 0) g_barrier = 0u; }
__global__ void loss1_k(const float* __restrict__ out, const int* __restrict__ y,
                        float* __restrict__ part){
    int b = blockIdx.x;
    const float* row = out + (size_t)b*OUTROW + (size_t)(NL-1)*NWD;
    __shared__ float red[256];
    float m = -1e30f;
    for (int i = threadIdx.x; i < NWD; i += 256) m = fmaxf(m, row[i]);
    red[threadIdx.x] = m; __syncthreads();
    for (int s = 128; s > 0; s >>= 1){ if (threadIdx.x < s) red[threadIdx.x] = fmaxf(red[threadIdx.x], red[threadIdx.x+s]); __syncthreads(); }
    m = red[0]; __syncthreads();
    float sum = 0.f;
    for (int i = threadIdx.x; i < NWD; i += 256) sum += expf(row[i] - m);
    red[threadIdx.x] = sum; __syncthreads();
    for (int s = 128; s > 0; s >>= 1){ if (threadIdx.x < s) red[threadIdx.x] += red[threadIdx.x+s]; __syncthreads(); }
    if (threadIdx.x == 0){
        int t = y[(NL-1)*NB + b];
        part[b] = -(row[t] - m - logf(red[0]));
    }
}
__global__ void loss2_k(const float* __restrict__ part, float* __restrict__ out){
    if (threadIdx.x == 0){
        float s = 0.f;
        for (int b = 0; b < NB; b++) s += part[b];
        out[(size_t)NB*NL*NWD] = s/(float)NB;
    }
}

extern "C" void kernel_launch(void* const* d_in, const int* in_sizes, int n_in,
                              void* d_out, int out_size){
    const float* x     = (const float*)d_in[0];
    const int*   y     = (const int*)  d_in[1];
    const float* Wih_v = (const float*)d_in[2];
    const float* Whh_v = (const float*)d_in[3];
    const float* bih_v = (const float*)d_in[4];
    const float* bhh_v = (const float*)d_in[5];
    const float* Wih_c = (const float*)d_in[6];
    const float* Whh_c = (const float*)d_in[7];
    const float* bih_c = (const float*)d_in[8];
    const float* bhh_c = (const float*)d_in[9];
    const float* Wout  = (const float*)d_in[10];
    const float* bout  = (const float*)d_in[11];
    float* out = (float*)d_out;

    float *gi, *gic, *enc, *h0, *hvall, *hcall, *lp;
    __nv_bfloat16 *xh, *xl, *wh, *wl, *hch, *hcl, *woh, *wol;
    __nv_bfloat16 *ench, *encl, *wch, *wcl, *whhch, *whhcl;
    cudaGetSymbolAddress((void**)&gi,    g_gi);
    cudaGetSymbolAddress((void**)&gic,   g_gic);
    cudaGetSymbolAddress((void**)&enc,   g_enc);
    cudaGetSymbolAddress((void**)&h0,    g_h0);
    cudaGetSymbolAddress((void**)&hvall, g_hvall);
    cudaGetSymbolAddress((void**)&hcall, g_hcall);
    cudaGetSymbolAddress((void**)&lp,    g_lpart);
    cudaGetSymbolAddress((void**)&xh,    g_xh);
    cudaGetSymbolAddress((void**)&xl,    g_xl);
    cudaGetSymbolAddress((void**)&wh,    g_wh);
    cudaGetSymbolAddress((void**)&wl,    g_wl);
    cudaGetSymbolAddress((void**)&hch,   g_hch);
    cudaGetSymbolAddress((void**)&hcl,   g_hcl);
    cudaGetSymbolAddress((void**)&woh,   g_woh);
    cudaGetSymbolAddress((void**)&wol,   g_wol);
    cudaGetSymbolAddress((void**)&ench,  g_ench);
    cudaGetSymbolAddress((void**)&encl,  g_encl);
    cudaGetSymbolAddress((void**)&wch,   g_wch);
    cudaGetSymbolAddress((void**)&wcl,   g_wcl);
    cudaGetSymbolAddress((void**)&whhch, g_whhch);
    cudaGetSymbolAddress((void**)&whhcl, g_whhcl);

    cudaFuncSetAttribute(scan_k, cudaFuncAttributeMaxDynamicSharedMemorySize, SMEM_BYTES);

    init_k<<<(NB*NWD + 255)/256, 256>>>(out);

    // one-time weight/input splits
    convx_k<<<((size_t)NT*NB*NF/4 + 255)/256, 256>>>(x, xh, xl);
    convg_k<<<((size_t)NG*NF/4 + 255)/256, 256>>>(Wih_v, wh, wl, (size_t)NG*NF/4);
    convg_k<<<((size_t)NWD*NH/4 + 255)/256, 256>>>(Wout, woh, wol, (size_t)NWD*NH/4);
    convs_k<<<((size_t)NG*NH/4 + 255)/256, 256>>>(Wih_c, NH+NWD, NG, NH, wch, wcl);
    convg_k<<<((size_t)NG*NH/4 + 255)/256, 256>>>(Whh_c, whhch, whhcl, (size_t)NG*NH/4);

    // gi_v via HMMA
    mmagemm_k<<<dim3(NG/128, NT*NB/128), 256>>>(xh, xl, wh, wl, bih_v, gi,
        NF, NT*NB, NG, NG, 0);

    // encoder-v
    scan_k<<<128, 256, SMEM_BYTES>>>(Whh_v, bhh_v, nullptr, gi, h0, enc, NT);

    // gi_c via HMMA: split enc, then (5120 x 1536 x 512)
    convg_k<<<((size_t)NT*NB*NH/4 + 255)/256, 256>>>(enc, ench, encl, (size_t)NT*NB*NH/4);
    mmagemm_k<<<dim3(NG/128, NT*NB/128), 256>>>(ench, encl, wch, wcl, bih_c, gic,
        NH, NT*NB, NG, NG, 0);

    bar0_k<<<1, 32>>>();
    scan_k<<<128, 256, SMEM_BYTES>>>(Whh_c, bhh_c, nullptr, gic, h0, gi, NT);

    bar0_k<<<1, 32>>>();
    scan_k<<<128, 256, SMEM_BYTES>>>(Whh_v, bhh_v, bih_v, nullptr,
        gi + (size_t)(NT-1)*BHSZ, hvall, NL-1);

    // batched decoder gi/gh via HMMA: split hvall (2048 x 512)
    convg_k<<<((size_t)(NL-1)*BHSZ/4 + 255)/256, 256>>>(hvall, hch, hcl, (size_t)(NL-1)*BHSZ/4);
    mmagemm_k<<<dim3(NG/128, 16), 256>>>(hch, hcl, wch, wcl, bih_c, gic,
        NH, (NL-1)*NB, NG, NG, 0);
    mmagemm_k<<<dim3(NG/128, 16), 256>>>(hch, hcl, whhch, whhcl, bhh_c, gi,
        NH, (NL-1)*NB, NG, NG, 0);
    dec_gates_k<<<((NL-1)*BHSZ + 255)/256, 256>>>(gic, gi, hvall, Wih_c, y, hcall);
    // logits on HMMA (hch/hcl reused for hcall split)
    convg_k<<<((size_t)(NL-1)*BHSZ/4 + 255)/256, 256>>>(hcall, hch, hcl, (size_t)(NL-1)*BHSZ/4);
    mmagemm_k<<<dim3((NWD + 127)/128, ((NL-1)*NB + 127)/128), 256>>>(hch, hcl, woh, wol, bout, out,
        NH, (NL-1)*NB, NWD, 0, 1);

    loss1_k<<<NB, 256>>>(out, y, lp);
    loss2_k<<<1, 32>>>(lp, out);
}